// round 14
// baseline (speedup 1.0000x reference)
#include <cuda_runtime.h>
#include <cuda_fp16.h>
#include <cstdint>

#define NB 16384
#define NE 256
#define NV 512
#define NT 16

// ---------------- scratch ----------------
__device__ __half g_st_h[2][NB * NE];
__device__ __half g_st_l[2][NB * NE];
__device__ __half g_GN_h[768 * 256];
__device__ __half g_GN_l[768 * 256];
__device__ __half g_Wo_h[NV * NE];
__device__ __half g_Wo_l[NV * NE];
__device__ float g_WihT[256 * 768];
__device__ float g_T[512 * 768];
__device__ float g_noiseAll[NT][NB * NV];   // EXACT gumbel noise (written by K1's noise CTAs)
__device__ float4 g_partA[NB * 4];          // (bestval, idx-bits, x_best, M) per vblk
__device__ float g_partB[NB * 4];           // sumexp per vblk
__device__ int g_alive[2][NB];
__device__ int g_N[NB];
__device__ float g_logp[NB];
__device__ uint32_t g_keys[NT][2];

#define SWM(row, g) ((((row) * 4) + ((g) ^ ((((row) >> 1)) & 3))) * 16)
#define TINYF 1.17549435e-38f

__device__ __forceinline__ uint32_t smem_u32(const void* p) {
    uint32_t a;
    asm("{ .reg .u64 t; cvta.to.shared.u64 t, %1; cvt.u32.u64 %0, t; }" : "=r"(a) : "l"(p));
    return a;
}
__device__ __forceinline__ void cpa16(uint32_t s, const void* g) {
    asm volatile("cp.async.ca.shared.global [%0], [%1], 16;" :: "r"(s), "l"(g));
}
__device__ __forceinline__ void ldm4(uint32_t* r, uint32_t a) {
    asm volatile("ldmatrix.sync.aligned.m8n8.x4.shared.b16 {%0,%1,%2,%3}, [%4];"
                 : "=r"(r[0]), "=r"(r[1]), "=r"(r[2]), "=r"(r[3]) : "r"(a));
}
__device__ __forceinline__ void ldm2(uint32_t* r, uint32_t a) {
    asm volatile("ldmatrix.sync.aligned.m8n8.x2.shared.b16 {%0,%1}, [%2];"
                 : "=r"(r[0]), "=r"(r[1]) : "r"(a));
}
__device__ __forceinline__ void mma16816(float* c, const uint32_t* a, const uint32_t* b) {
    asm volatile(
        "mma.sync.aligned.m16n8k16.row.col.f32.f16.f16.f32 "
        "{%0,%1,%2,%3}, {%4,%5,%6,%7}, {%8,%9}, {%0,%1,%2,%3};"
        : "+f"(c[0]), "+f"(c[1]), "+f"(c[2]), "+f"(c[3])
        : "r"(a[0]), "r"(a[1]), "r"(a[2]), "r"(a[3]), "r"(b[0]), "r"(b[1]));
}
__device__ __forceinline__ void split2(float v, __half& h, __half& l) {
    h = __float2half(v);
    l = __float2half(v - __half2float(h));
}

// ---------------- threefry ----------------
__device__ __forceinline__ uint32_t rotl32(uint32_t v, int r) {
    return (v << r) | (v >> (32 - r));
}
__device__ __forceinline__ void tfry(uint32_t k0, uint32_t k1,
                                     uint32_t c0, uint32_t c1,
                                     uint32_t& o0, uint32_t& o1) {
    uint32_t k2 = k0 ^ k1 ^ 0x1BD11BDAu;
    uint32_t x0 = c0 + k0, x1 = c1 + k1;
#define R4(a,b,c,d) { x0+=x1; x1=rotl32(x1,a); x1^=x0; x0+=x1; x1=rotl32(x1,b); x1^=x0; \
                      x0+=x1; x1=rotl32(x1,c); x1^=x0; x0+=x1; x1=rotl32(x1,d); x1^=x0; }
    R4(13,15,26,6)  x0 += k1; x1 += k2 + 1u;
    R4(17,29,16,24) x0 += k2; x1 += k0 + 2u;
    R4(13,15,26,6)  x0 += k0; x1 += k1 + 3u;
    R4(17,29,16,24) x0 += k1; x1 += k2 + 4u;
    R4(13,15,26,6)  x0 += k2; x1 += k0 + 5u;
#undef R4
    o0 = x0; o1 = x1;
}

__device__ __forceinline__ int combine_row(int grow, float* lp_out) {
    float4 pa[4];
    float sv[4];
#pragma unroll
    for (int i = 0; i < 4; i++) {
        pa[i] = g_partA[grow * 4 + i];
        sv[i] = g_partB[grow * 4 + i];
    }
    float M = fmaxf(fmaxf(pa[0].w, pa[1].w), fmaxf(pa[2].w, pa[3].w));
    float S = 0.0f;
#pragma unroll
    for (int i = 0; i < 4; i++) S += sv[i] * __expf(pa[i].w - M);
    float bv = pa[0].x;
    int bi = __float_as_int(pa[0].y);
    float bx = pa[0].z;
#pragma unroll
    for (int i = 1; i < 4; i++) {
        int oi = __float_as_int(pa[i].y);
        if (pa[i].x > bv || (pa[i].x == bv && oi < bi)) {
            bv = pa[i].x; bi = oi; bx = pa[i].z;
        }
    }
    *lp_out = bx - M - logf(S);
    return bi;
}

// ---------------- prep ----------------
__global__ void prep_kernel(const float* __restrict__ Wih,
                            const float* __restrict__ Whh,
                            const float* __restrict__ Wout) {
    int tid = blockIdx.x * blockDim.x + threadIdx.x;
    int stride = gridDim.x * blockDim.x;
    for (int i = tid; i < 768 * 256; i += stride) {
        __half h, l; split2(Whh[i], h, l);
        g_GN_h[i] = h; g_GN_l[i] = l;
    }
    for (int i = tid; i < 256 * 768; i += stride) {
        int k = i / 768, np = i - k * 768;
        g_WihT[i] = Wih[np * 256 + k];
    }
    for (int i = tid; i < NV * NE; i += stride) {
        __half h, l;
        split2(Wout[i], h, l);
        g_Wo_h[i] = h; g_Wo_l[i] = l;
    }
    if (blockIdx.x == 0 && threadIdx.x == 0) {
        for (int t = 0; t < NT; t++) {
            uint32_t a, b;
            tfry(0u, 42u, 0u, (uint32_t)t, a, b);
            g_keys[t][0] = a; g_keys[t][1] = b;
        }
    }
}

__global__ __launch_bounds__(256)
void tgemm_kernel(const float* __restrict__ d2e,
                  const float* __restrict__ bih,
                  const float* __restrict__ bhh) {
    __shared__ float es[8][256];
    int tokbase = blockIdx.x * 8;
    int tid = threadIdx.x;
    for (int i = tid; i < 8 * 256; i += 256)
        es[i >> 8][i & 255] = d2e[(tokbase + (i >> 8)) * 256 + (i & 255)];
    __syncthreads();
#pragma unroll
    for (int p = 0; p < 3; p++) {
        int np = tid + p * 256;
        float acc[8];
        float bias = bih[np] + (np < 512 ? bhh[np] : 0.0f);
#pragma unroll
        for (int t = 0; t < 8; t++) acc[t] = 0.0f;
        for (int k = 0; k < 256; k++) {
            float w = g_WihT[k * 768 + np];
#pragma unroll
            for (int t = 0; t < 8; t++) acc[t] += es[t][k] * w;
        }
#pragma unroll
        for (int t = 0; t < 8; t++)
            g_T[(tokbase + t) * 768 + np] = acc[t] + bias;
    }
}

__global__ void init_kernel(const int* __restrict__ actions,
                            const float* __restrict__ h1) {
    int tid = blockIdx.x * blockDim.x + threadIdx.x;
    int stride = gridDim.x * blockDim.x;
    for (int i = tid; i < NB * NE; i += stride) {
        int b = i >> 8, e = i & 255;
        float v = h1[actions[b] * NE + e];
        __half h, l; split2(v, h, l);
        g_st_h[0][i] = h; g_st_l[0][i] = l;
    }
    for (int i = tid; i < NB; i += stride) {
        g_alive[0][i] = 1; g_N[i] = NT; g_logp[i] = 0.0f;
    }
}

// ============ K1: [bx<8] combine(t-1) + state @ Whh^T + GRU epilogue
//              [bx>=8] co-resident noise CTAs: exact gumbel for step t ============
#define K1_STAGE 28672
#define K1_SMEM (3 * K1_STAGE + 512)
__global__ __launch_bounds__(256, 2)
void k1_mma(int t, const float* __restrict__ bhh, float* __restrict__ out) {
    extern __shared__ char smem[];
    const int tid = threadIdx.x;

    // ---- noise CTAs: fill g_noiseAll[t] using K1's idle issue slots ----
    if (blockIdx.x >= 8) {
        int nb = (blockIdx.x - 8) + 4 * blockIdx.y;   // 0..511
        const uint32_t k0 = g_keys[t][0], k1 = g_keys[t][1];
        float* __restrict__ dst = g_noiseAll[t];
#pragma unroll
        for (int k = 0; k < 16; k++) {
            uint32_t i4 = (uint32_t)nb * 4096u + (uint32_t)k * 256u + (uint32_t)tid;
            uint32_t base = i4 * 4u;
            float r[4];
#pragma unroll
            for (int q = 0; q < 4; q++) {
                uint32_t o0, o1;
                tfry(k0, k1, 0u, base + q, o0, o1);
                uint32_t bits = o0 ^ o1;
                float f = __uint_as_float((bits >> 9) | 0x3f800000u) - 1.0f;
                float u = fmaxf(TINYF, f * (1.0f - TINYF) + TINYF);
                r[q] = -logf(-logf(u));
            }
            *(float4*)&dst[base] = make_float4(r[0], r[1], r[2], r[3]);
        }
        return;
    }

    const uint32_t sbase = smem_u32(smem);
    const int lane = tid & 31, wid = tid >> 5;
    const int wm = wid & 3, wn = wid >> 2;
    const int j0 = blockIdx.x * 32;
    const int rbase = blockIdx.y * 128;
    const int cur = t & 1, nxt = cur ^ 1;
    int* tok_sm = (int*)(smem + 3 * K1_STAGE);

    const int arow = tid >> 1, ahalf = tid & 1;
    const uint32_t sw0 = SWM(arow, ahalf * 2);
    const uint32_t sw1 = SWM(arow, ahalf * 2 + 1);
    const size_t aoff = (size_t)(rbase + arow) * 256 + ahalf * 16;

    float acc[2][6][4];
#pragma unroll
    for (int i = 0; i < 2; i++)
#pragma unroll
        for (int j = 0; j < 6; j++)
#pragma unroll
            for (int q = 0; q < 4; q++) acc[i][j][q] = 0.0f;

    int b_half[3];
    size_t b_src[3];
    uint32_t b_dst[3];
#pragma unroll
    for (int i = 0; i < 3; i++) {
        int o = tid + 256 * i;
        int half = o >= 384;
        int rem = o - half * 384;
        int brow = rem >> 2, grp = rem & 3;
        b_half[i] = half;
        int grow = (brow >> 5) * 256 + j0 + (brow & 31);
        b_src[i] = (size_t)grow * 256 + grp * 8;
        b_dst[i] = 16384 + half * 6144 + SWM(brow, grp);
    }

    auto stage = [&](int c, int buf) {
        uint32_t ab = sbase + buf * K1_STAGE;
        size_t off = aoff + c * 32;
        cpa16(ab + sw0, g_st_h[cur] + off);
        cpa16(ab + sw1, g_st_h[cur] + off + 8);
        cpa16(ab + 8192 + sw0, g_st_l[cur] + off);
        cpa16(ab + 8192 + sw1, g_st_l[cur] + off + 8);
#pragma unroll
        for (int i = 0; i < 3; i++) {
            const __half* src = (b_half[i] ? g_GN_l : g_GN_h) + b_src[i] + c * 32;
            cpa16(ab + b_dst[i], src);
        }
    };

    stage(0, 0);
    asm volatile("cp.async.commit_group;");
    stage(1, 1);
    asm volatile("cp.async.commit_group;");

    if (tid < 128) {
        int grow = rbase + tid;
        int tok_out = 0;
        if (t > 0) {
            float lp;
            int tok = combine_row(grow, &lp);
            int alive = g_alive[(t - 1) & 1][grow];
            tok_out = alive ? tok : 0;
            if (blockIdx.x == 0) {
                if (alive) g_logp[grow] += lp;
                if (alive && tok == 0) g_N[grow] = t;
                g_alive[t & 1][grow] = (alive && tok != 0) ? 1 : 0;
                out[(size_t)grow * NT + (t - 1)] = (float)tok_out;
            }
        }
        tok_sm[tid] = tok_out;
    }

    for (int c = 0; c < 8; c++) {
        if (c < 7) asm volatile("cp.async.wait_group 1;");
        else       asm volatile("cp.async.wait_group 0;");
        __syncthreads();
        if (c < 6) {
            stage(c + 2, (c + 2) % 3);
            asm volatile("cp.async.commit_group;");
        }
        uint32_t ab = sbase + (c % 3) * K1_STAGE;
#pragma unroll
        for (int q = 0; q < 2; q++) {
            int gb = q * 2;
            uint32_t aAddr[2], bAddr[6];
            {
                int rl = wm * 32 + (lane & 15);
                int ga = gb + (lane >> 4);
#pragma unroll
                for (int mt = 0; mt < 2; mt++)
                    aAddr[mt] = ab + SWM(rl + mt * 16, ga);
                int rb0 = wn * 48 + (lane & 7);
                int gbb = gb + ((lane >> 3) & 1);
#pragma unroll
                for (int nt = 0; nt < 6; nt++)
                    bAddr[nt] = ab + 16384 + SWM(rb0 + nt * 8, gbb);
            }
            uint32_t af[2][4], bh[6][2], bl[6][2];
#pragma unroll
            for (int mt = 0; mt < 2; mt++) ldm4(af[mt], aAddr[mt]);
#pragma unroll
            for (int nt = 0; nt < 6; nt++) ldm2(bh[nt], bAddr[nt]);
#pragma unroll
            for (int mt = 0; mt < 2; mt++)
#pragma unroll
                for (int nt = 0; nt < 6; nt++) mma16816(acc[mt][nt], af[mt], bh[nt]);
#pragma unroll
            for (int nt = 0; nt < 6; nt++) ldm2(bl[nt], bAddr[nt] + 6144);
#pragma unroll
            for (int mt = 0; mt < 2; mt++)
#pragma unroll
                for (int nt = 0; nt < 6; nt++) mma16816(acc[mt][nt], af[mt], bl[nt]);
#pragma unroll
            for (int mt = 0; mt < 2; mt++) ldm4(af[mt], aAddr[mt] + 8192);
#pragma unroll
            for (int mt = 0; mt < 2; mt++)
#pragma unroll
                for (int nt = 0; nt < 6; nt++) mma16816(acc[mt][nt], af[mt], bh[nt]);
        }
    }

    float* Cs = (float*)smem;
    __syncthreads();
#pragma unroll
    for (int mt = 0; mt < 2; mt++)
#pragma unroll
        for (int nt = 0; nt < 6; nt++) {
            int r0 = wm * 32 + mt * 16 + (lane >> 2);
            int c0 = wn * 48 + nt * 8 + (lane & 3) * 2;
            Cs[r0 * 100 + c0] = acc[mt][nt][0];
            Cs[r0 * 100 + c0 + 1] = acc[mt][nt][1];
            Cs[(r0 + 8) * 100 + c0] = acc[mt][nt][2];
            Cs[(r0 + 8) * 100 + c0 + 1] = acc[mt][nt][3];
        }
    __syncthreads();
    {
        int jl = tid & 31, rseg = tid >> 5;
        int j = j0 + jl;
        float bhn = bhh[512 + j];
#pragma unroll
        for (int rr = 0; rr < 16; rr++) {
            int r = rseg * 16 + rr;
            int grow = rbase + r;
            int tok = tok_sm[r];
            const float* Trow = g_T + (size_t)tok * 768;
            float cr = Cs[r * 100 + jl] + Trow[j];
            float cz = Cs[r * 100 + 32 + jl] + Trow[256 + j];
            float cn = Cs[r * 100 + 64 + jl] + bhn;
            size_t so = (size_t)grow * 256 + j;
            float hold = __half2float(g_st_h[cur][so]) + __half2float(g_st_l[cur][so]);
            float rg = 1.0f / (1.0f + expf(-cr));
            float zg = 1.0f / (1.0f + expf(-cz));
            float nn = tanhf(Trow[512 + j] + rg * cn);
            float v = (1.0f - zg) * nn + zg * hold;
            __half hh, hl;
            split2(v, hh, hl);
            g_st_h[nxt][so] = hh;
            g_st_l[nxt][so] = hl;
        }
    }
}

// ============ K2: logits GEMM + fused gumbel-argmax partials ============
#define K2_SMEM (3 * 32768)
__global__ __launch_bounds__(256, 2)
void k2_mma(int t, const float* __restrict__ bout) {
    extern __shared__ char smem[];
    const uint32_t sbase = smem_u32(smem);
    const int tid = threadIdx.x;
    const int lane = tid & 31, wid = tid >> 5;
    const int wm = wid & 1, wn = wid >> 1;
    const int v0 = blockIdx.x * 128;
    const int rbase = blockIdx.y * 128;
    const int nxt = (t + 1) & 1;
    const float* __restrict__ noise = g_noiseAll[t];

    const int arow = tid >> 1, ahalf = tid & 1;
    const uint32_t sw0 = SWM(arow, ahalf * 2);
    const uint32_t sw1 = SWM(arow, ahalf * 2 + 1);

    float acc[4][4][4];
#pragma unroll
    for (int i = 0; i < 4; i++)
#pragma unroll
        for (int j = 0; j < 4; j++)
#pragma unroll
            for (int q = 0; q < 4; q++) acc[i][j][q] = 0.0f;

    auto stage = [&](int c, int buf) {
        uint32_t ab = sbase + buf * 32768;
        size_t off = (size_t)(rbase + arow) * 256 + c * 32 + ahalf * 16;
        cpa16(ab + sw0, g_st_h[nxt] + off);
        cpa16(ab + sw1, g_st_h[nxt] + off + 8);
        cpa16(ab + 8192 + sw0, g_st_l[nxt] + off);
        cpa16(ab + 8192 + sw1, g_st_l[nxt] + off + 8);
        size_t offb = (size_t)(v0 + arow) * 256 + c * 32 + ahalf * 16;
        cpa16(ab + 16384 + sw0, g_Wo_h + offb);
        cpa16(ab + 16384 + sw1, g_Wo_h + offb + 8);
        cpa16(ab + 24576 + sw0, g_Wo_l + offb);
        cpa16(ab + 24576 + sw1, g_Wo_l + offb + 8);
    };

    stage(0, 0);
    asm volatile("cp.async.commit_group;");
    stage(1, 1);
    asm volatile("cp.async.commit_group;");

    for (int c = 0; c < 8; c++) {
        if (c < 7) asm volatile("cp.async.wait_group 1;");
        else       asm volatile("cp.async.wait_group 0;");
        __syncthreads();
        if (c < 6) {
            stage(c + 2, (c + 2) % 3);
            asm volatile("cp.async.commit_group;");
        }
        uint32_t ab = sbase + (c % 3) * 32768;
#pragma unroll
        for (int q = 0; q < 2; q++) {
            int gb = q * 2;
            uint32_t aAddr[4], bAddr[4];
            {
                int rl = wm * 64 + (lane & 15);
                int ga = gb + (lane >> 4);
#pragma unroll
                for (int mt = 0; mt < 4; mt++)
                    aAddr[mt] = ab + SWM(rl + mt * 16, ga);
                int rb = wn * 32 + (lane & 7);
                int gbb = gb + ((lane >> 3) & 1);
#pragma unroll
                for (int nt = 0; nt < 4; nt++)
                    bAddr[nt] = ab + 16384 + SWM(rb + nt * 8, gbb);
            }
            uint32_t af[4][4], bh[4][2], bl[4][2];
#pragma unroll
            for (int mt = 0; mt < 4; mt++) ldm4(af[mt], aAddr[mt]);
#pragma unroll
            for (int nt = 0; nt < 4; nt++) ldm2(bh[nt], bAddr[nt]);
#pragma unroll
            for (int mt = 0; mt < 4; mt++)
#pragma unroll
                for (int nt = 0; nt < 4; nt++) mma16816(acc[mt][nt], af[mt], bh[nt]);
#pragma unroll
            for (int nt = 0; nt < 4; nt++) ldm2(bl[nt], bAddr[nt] + 8192);
#pragma unroll
            for (int mt = 0; mt < 4; mt++)
#pragma unroll
                for (int nt = 0; nt < 4; nt++) mma16816(acc[mt][nt], af[mt], bl[nt]);
#pragma unroll
            for (int mt = 0; mt < 4; mt++) ldm4(af[mt], aAddr[mt] + 8192);
#pragma unroll
            for (int mt = 0; mt < 4; mt++)
#pragma unroll
                for (int nt = 0; nt < 4; nt++) mma16816(acc[mt][nt], af[mt], bh[nt]);
        }
    }

    // ---- epilogue: bias, row-max, gumbel-argmax + sumexp partials ----
#pragma unroll
    for (int nt = 0; nt < 4; nt++) {
        int c0 = v0 + wn * 32 + nt * 8 + (lane & 3) * 2;
        float b0 = bout[c0], b1 = bout[c0 + 1];
#pragma unroll
        for (int mt = 0; mt < 4; mt++) {
            acc[mt][nt][0] += b0; acc[mt][nt][1] += b1;
            acc[mt][nt][2] += b0; acc[mt][nt][3] += b1;
        }
    }
    __syncthreads();
    float* msm = (float*)smem;          // [4][128]
    float* vsm = msm + 512;
    float* xsm = vsm + 512;
    float* ssm = xsm + 512;
    int*   ism = (int*)(ssm + 512);

#pragma unroll
    for (int mt = 0; mt < 4; mt++) {
        float mA = -3.4e38f, mB = -3.4e38f;
#pragma unroll
        for (int nt = 0; nt < 4; nt++) {
            mA = fmaxf(mA, fmaxf(acc[mt][nt][0], acc[mt][nt][1]));
            mB = fmaxf(mB, fmaxf(acc[mt][nt][2], acc[mt][nt][3]));
        }
#pragma unroll
        for (int off = 1; off <= 2; off <<= 1) {
            mA = fmaxf(mA, __shfl_xor_sync(0xffffffffu, mA, off));
            mB = fmaxf(mB, __shfl_xor_sync(0xffffffffu, mB, off));
        }
        if ((lane & 3) == 0) {
            int r0 = wm * 64 + mt * 16 + (lane >> 2);
            msm[wn * 128 + r0] = mA;
            msm[wn * 128 + r0 + 8] = mB;
        }
    }
    __syncthreads();
#pragma unroll
    for (int mt = 0; mt < 4; mt++) {
        int r0 = wm * 64 + mt * 16 + (lane >> 2), r1 = r0 + 8;
        float MA = fmaxf(fmaxf(msm[r0], msm[128 + r0]), fmaxf(msm[256 + r0], msm[384 + r0]));
        float MB = fmaxf(fmaxf(msm[r1], msm[128 + r1]), fmaxf(msm[256 + r1], msm[384 + r1]));
        int growA = rbase + r0, growB = rbase + r1;
        float sA = 0.0f, sB = 0.0f;
        float bvA = -3.4e38f, bvB = -3.4e38f, bxA = 0.0f, bxB = 0.0f;
        int biA = 0, biB = 0;
#pragma unroll
        for (int nt = 0; nt < 4; nt++) {
            int c0 = v0 + wn * 32 + nt * 8 + (lane & 3) * 2;
            float2 nA = *(const float2*)&noise[(size_t)growA * NV + c0];
            float2 nB = *(const float2*)&noise[(size_t)growB * NV + c0];
            float x0 = acc[mt][nt][0], x1 = acc[mt][nt][1];
            float vA0 = x0 + nA.x, vA1 = x1 + nA.y;
            if (vA0 > bvA) { bvA = vA0; biA = c0; bxA = x0; }
            if (vA1 > bvA) { bvA = vA1; biA = c0 + 1; bxA = x1; }
            sA += __expf(x0 - MA) + __expf(x1 - MA);
            float x2 = acc[mt][nt][2], x3 = acc[mt][nt][3];
            float vB0 = x2 + nB.x, vB1 = x3 + nB.y;
            if (vB0 > bvB) { bvB = vB0; biB = c0; bxB = x2; }
            if (vB1 > bvB) { bvB = vB1; biB = c0 + 1; bxB = x3; }
            sB += __expf(x2 - MB) + __expf(x3 - MB);
        }
#pragma unroll
        for (int off = 1; off <= 2; off <<= 1) {
            sA += __shfl_xor_sync(0xffffffffu, sA, off);
            sB += __shfl_xor_sync(0xffffffffu, sB, off);
            float ov = __shfl_xor_sync(0xffffffffu, bvA, off);
            int oi = __shfl_xor_sync(0xffffffffu, biA, off);
            float ox = __shfl_xor_sync(0xffffffffu, bxA, off);
            if (ov > bvA || (ov == bvA && oi < biA)) { bvA = ov; biA = oi; bxA = ox; }
            ov = __shfl_xor_sync(0xffffffffu, bvB, off);
            oi = __shfl_xor_sync(0xffffffffu, biB, off);
            ox = __shfl_xor_sync(0xffffffffu, bxB, off);
            if (ov > bvB || (ov == bvB && oi < biB)) { bvB = ov; biB = oi; bxB = ox; }
        }
        if ((lane & 3) == 0) {
            vsm[wn * 128 + r0] = bvA; ism[wn * 128 + r0] = biA;
            xsm[wn * 128 + r0] = bxA; ssm[wn * 128 + r0] = sA;
            vsm[wn * 128 + r1] = bvB; ism[wn * 128 + r1] = biB;
            xsm[wn * 128 + r1] = bxB; ssm[wn * 128 + r1] = sB;
        }
    }
    __syncthreads();
    if (tid < 128) {
        int r = tid, grow = rbase + r;
        float M = fmaxf(fmaxf(msm[r], msm[128 + r]), fmaxf(msm[256 + r], msm[384 + r]));
        float S = ssm[r] + ssm[128 + r] + ssm[256 + r] + ssm[384 + r];
        float bv = vsm[r]; int bi = ism[r]; float bx = xsm[r];
#pragma unroll
        for (int w = 1; w < 4; w++) {
            float ov = vsm[w * 128 + r]; int oi = ism[w * 128 + r];
            if (ov > bv || (ov == bv && oi < bi)) { bv = ov; bi = oi; bx = xsm[w * 128 + r]; }
        }
        g_partA[grow * 4 + blockIdx.x] = make_float4(bv, __int_as_float(bi), bx, M);
        g_partB[grow * 4 + blockIdx.x] = S;
    }
}

// ---------------- fin: combine step 15 + outputs ----------------
__global__ void fin_kernel(float* __restrict__ out) {
    int b = blockIdx.x * blockDim.x + threadIdx.x;
    if (b < NB) {
        float lp;
        int tok = combine_row(b, &lp);
        int alive = g_alive[1][b];
        int tok_out = alive ? tok : 0;
        float logp = g_logp[b] + (alive ? lp : 0.0f);
        out[(size_t)b * NT + 15] = (float)tok_out;
        out[NB * NT + b] = (float)g_N[b];
        out[NB * NT + NB + b] = logp;
    }
}

extern "C" void kernel_launch(void* const* d_in, const int* in_sizes, int n_in,
                              void* d_out, int out_size) {
    const int* actions = (const int*)d_in[0];
    const float* h1 = (const float*)d_in[2];
    const float* d2e = (const float*)d_in[3];
    const float* Wih = (const float*)d_in[4];
    const float* Whh = (const float*)d_in[5];
    const float* bih = (const float*)d_in[6];
    const float* bhh = (const float*)d_in[7];
    const float* Wout = (const float*)d_in[8];
    const float* bout = (const float*)d_in[9];
    float* out = (float*)d_out;

    cudaFuncSetAttribute(k1_mma, cudaFuncAttributeMaxDynamicSharedMemorySize, K1_SMEM);
    cudaFuncSetAttribute(k2_mma, cudaFuncAttributeMaxDynamicSharedMemorySize, K2_SMEM);

    prep_kernel<<<1024, 256>>>(Wih, Whh, Wout);
    tgemm_kernel<<<64, 256>>>(d2e, bih, bhh);
    init_kernel<<<2048, 256>>>(actions, h1);

    for (int t = 0; t < NT; t++) {
        k1_mma<<<dim3(12, 128), 256, K1_SMEM>>>(t, bhh, out);
        k2_mma<<<dim3(4, 128), 256, K2_SMEM>>>(t, bout);
    }
    fin_kernel<<<64, 256>>>(out);
}

// round 15
// speedup vs baseline: 1.0694x; 1.0694x over previous
#include <cuda_runtime.h>
#include <cuda_fp16.h>
#include <cstdint>

#define NB 16384
#define NE 256
#define NV 512
#define NT 16

// ---------------- scratch ----------------
__device__ __half g_st_h[2][NB * NE];
__device__ __half g_st_l[2][NB * NE];
__device__ __half g_GN_h[768 * 256];
__device__ __half g_GN_l[768 * 256];
__device__ __half g_Wo_h[NV * NE];
__device__ __half g_Wo_l[NV * NE];
__device__ float g_WihT[256 * 768];
__device__ float g_T[512 * 768];
__device__ float g_noiseAll[NT][NB * NV];   // EXACT gumbel noise (side stream, co-resident)
__device__ float4 g_partA[NB * 4];          // (bestval, idx-bits, x_best, M) per vblk
__device__ float g_partB[NB * 4];           // sumexp per vblk
__device__ int g_alive[2][NB];
__device__ int g_N[NB];
__device__ float g_logp[NB];
__device__ uint32_t g_keys[NT][2];

#define SWM(row, g) ((((row) * 4) + ((g) ^ ((((row) >> 1)) & 3))) * 16)
#define TINYF 1.17549435e-38f

__device__ __forceinline__ uint32_t smem_u32(const void* p) {
    uint32_t a;
    asm("{ .reg .u64 t; cvta.to.shared.u64 t, %1; cvt.u32.u64 %0, t; }" : "=r"(a) : "l"(p));
    return a;
}
__device__ __forceinline__ void cpa16(uint32_t s, const void* g) {
    asm volatile("cp.async.ca.shared.global [%0], [%1], 16;" :: "r"(s), "l"(g));
}
__device__ __forceinline__ void ldm4(uint32_t* r, uint32_t a) {
    asm volatile("ldmatrix.sync.aligned.m8n8.x4.shared.b16 {%0,%1,%2,%3}, [%4];"
                 : "=r"(r[0]), "=r"(r[1]), "=r"(r[2]), "=r"(r[3]) : "r"(a));
}
__device__ __forceinline__ void ldm2(uint32_t* r, uint32_t a) {
    asm volatile("ldmatrix.sync.aligned.m8n8.x2.shared.b16 {%0,%1}, [%2];"
                 : "=r"(r[0]), "=r"(r[1]) : "r"(a));
}
__device__ __forceinline__ void mma16816(float* c, const uint32_t* a, const uint32_t* b) {
    asm volatile(
        "mma.sync.aligned.m16n8k16.row.col.f32.f16.f16.f32 "
        "{%0,%1,%2,%3}, {%4,%5,%6,%7}, {%8,%9}, {%0,%1,%2,%3};"
        : "+f"(c[0]), "+f"(c[1]), "+f"(c[2]), "+f"(c[3])
        : "r"(a[0]), "r"(a[1]), "r"(a[2]), "r"(a[3]), "r"(b[0]), "r"(b[1]));
}
__device__ __forceinline__ void split2(float v, __half& h, __half& l) {
    h = __float2half(v);
    l = __float2half(v - __half2float(h));
}

// ---------------- threefry ----------------
__device__ __forceinline__ uint32_t rotl32(uint32_t v, int r) {
    return (v << r) | (v >> (32 - r));
}
__device__ __forceinline__ void tfry(uint32_t k0, uint32_t k1,
                                     uint32_t c0, uint32_t c1,
                                     uint32_t& o0, uint32_t& o1) {
    uint32_t k2 = k0 ^ k1 ^ 0x1BD11BDAu;
    uint32_t x0 = c0 + k0, x1 = c1 + k1;
#define R4(a,b,c,d) { x0+=x1; x1=rotl32(x1,a); x1^=x0; x0+=x1; x1=rotl32(x1,b); x1^=x0; \
                      x0+=x1; x1=rotl32(x1,c); x1^=x0; x0+=x1; x1=rotl32(x1,d); x1^=x0; }
    R4(13,15,26,6)  x0 += k1; x1 += k2 + 1u;
    R4(17,29,16,24) x0 += k2; x1 += k0 + 2u;
    R4(13,15,26,6)  x0 += k0; x1 += k1 + 3u;
    R4(17,29,16,24) x0 += k1; x1 += k2 + 4u;
    R4(13,15,26,6)  x0 += k2; x1 += k0 + 5u;
#undef R4
    o0 = x0; o1 = x1;
}

__device__ __forceinline__ int combine_row(int grow, float* lp_out) {
    float4 pa[4];
    float sv[4];
#pragma unroll
    for (int i = 0; i < 4; i++) {
        pa[i] = g_partA[grow * 4 + i];
        sv[i] = g_partB[grow * 4 + i];
    }
    float M = fmaxf(fmaxf(pa[0].w, pa[1].w), fmaxf(pa[2].w, pa[3].w));
    float S = 0.0f;
#pragma unroll
    for (int i = 0; i < 4; i++) S += sv[i] * __expf(pa[i].w - M);
    float bv = pa[0].x;
    int bi = __float_as_int(pa[0].y);
    float bx = pa[0].z;
#pragma unroll
    for (int i = 1; i < 4; i++) {
        int oi = __float_as_int(pa[i].y);
        if (pa[i].x > bv || (pa[i].x == bv && oi < bi)) {
            bv = pa[i].x; bi = oi; bx = pa[i].z;
        }
    }
    *lp_out = bx - M - logf(S);
    return bi;
}

// ---------------- noise: EXACT gumbel, small CTAs that co-reside with GEMMs ----------------
__global__ void __launch_bounds__(128) noise_kernel(int t) {
    const uint32_t k0 = g_keys[t][0], k1 = g_keys[t][1];
    float* __restrict__ dst = g_noiseAll[t];
#pragma unroll
    for (int k = 0; k < 8; k++) {
        uint32_t i4 = (uint32_t)blockIdx.x * 1024u + (uint32_t)k * 128u + (uint32_t)threadIdx.x;
        uint32_t base = i4 * 4u;
        float r[4];
#pragma unroll
        for (int q = 0; q < 4; q++) {
            uint32_t o0, o1;
            tfry(k0, k1, 0u, base + q, o0, o1);
            uint32_t bits = o0 ^ o1;
            float f = __uint_as_float((bits >> 9) | 0x3f800000u) - 1.0f;
            float u = fmaxf(TINYF, f * (1.0f - TINYF) + TINYF);
            r[q] = -logf(-logf(u));
        }
        *(float4*)&dst[base] = make_float4(r[0], r[1], r[2], r[3]);
    }
}

// ---------------- prep ----------------
__global__ void prep_kernel(const float* __restrict__ Wih,
                            const float* __restrict__ Whh,
                            const float* __restrict__ Wout) {
    int tid = blockIdx.x * blockDim.x + threadIdx.x;
    int stride = gridDim.x * blockDim.x;
    for (int i = tid; i < 768 * 256; i += stride) {
        __half h, l; split2(Whh[i], h, l);
        g_GN_h[i] = h; g_GN_l[i] = l;
    }
    for (int i = tid; i < 256 * 768; i += stride) {
        int k = i / 768, np = i - k * 768;
        g_WihT[i] = Wih[np * 256 + k];
    }
    for (int i = tid; i < NV * NE; i += stride) {
        __half h, l;
        split2(Wout[i], h, l);
        g_Wo_h[i] = h; g_Wo_l[i] = l;
    }
    if (blockIdx.x == 0 && threadIdx.x == 0) {
        for (int t = 0; t < NT; t++) {
            uint32_t a, b;
            tfry(0u, 42u, 0u, (uint32_t)t, a, b);
            g_keys[t][0] = a; g_keys[t][1] = b;
        }
    }
}

__global__ __launch_bounds__(256)
void tgemm_kernel(const float* __restrict__ d2e,
                  const float* __restrict__ bih,
                  const float* __restrict__ bhh) {
    __shared__ float es[8][256];
    int tokbase = blockIdx.x * 8;
    int tid = threadIdx.x;
    for (int i = tid; i < 8 * 256; i += 256)
        es[i >> 8][i & 255] = d2e[(tokbase + (i >> 8)) * 256 + (i & 255)];
    __syncthreads();
#pragma unroll
    for (int p = 0; p < 3; p++) {
        int np = tid + p * 256;
        float acc[8];
        float bias = bih[np] + (np < 512 ? bhh[np] : 0.0f);
#pragma unroll
        for (int t = 0; t < 8; t++) acc[t] = 0.0f;
        for (int k = 0; k < 256; k++) {
            float w = g_WihT[k * 768 + np];
#pragma unroll
            for (int t = 0; t < 8; t++) acc[t] += es[t][k] * w;
        }
#pragma unroll
        for (int t = 0; t < 8; t++)
            g_T[(tokbase + t) * 768 + np] = acc[t] + bias;
    }
}

__global__ void init_kernel(const int* __restrict__ actions,
                            const float* __restrict__ h1) {
    int tid = blockIdx.x * blockDim.x + threadIdx.x;
    int stride = gridDim.x * blockDim.x;
    for (int i = tid; i < NB * NE; i += stride) {
        int b = i >> 8, e = i & 255;
        float v = h1[actions[b] * NE + e];
        __half h, l; split2(v, h, l);
        g_st_h[0][i] = h; g_st_l[0][i] = l;
    }
    for (int i = tid; i < NB; i += stride) {
        g_alive[0][i] = 1; g_N[i] = NT; g_logp[i] = 0.0f;
    }
}

// ============ K1: combine(t-1) + state @ Whh^T + GRU epilogue ============
#define K1_STAGE 28672
#define K1_SMEM (3 * K1_STAGE + 512)
__global__ void __maxnreg__(120) k1_mma(int t, const float* __restrict__ bhh,
                                        float* __restrict__ out) {
    extern __shared__ char smem[];
    const uint32_t sbase = smem_u32(smem);
    const int tid = threadIdx.x;
    const int lane = tid & 31, wid = tid >> 5;
    const int wm = wid & 3, wn = wid >> 2;
    const int j0 = blockIdx.x * 32;
    const int rbase = blockIdx.y * 128;
    const int cur = t & 1, nxt = cur ^ 1;
    int* tok_sm = (int*)(smem + 3 * K1_STAGE);

    const int arow = tid >> 1, ahalf = tid & 1;
    const uint32_t sw0 = SWM(arow, ahalf * 2);
    const uint32_t sw1 = SWM(arow, ahalf * 2 + 1);
    const size_t aoff = (size_t)(rbase + arow) * 256 + ahalf * 16;

    float acc[2][6][4];
#pragma unroll
    for (int i = 0; i < 2; i++)
#pragma unroll
        for (int j = 0; j < 6; j++)
#pragma unroll
            for (int q = 0; q < 4; q++) acc[i][j][q] = 0.0f;

    int b_half[3];
    size_t b_src[3];
    uint32_t b_dst[3];
#pragma unroll
    for (int i = 0; i < 3; i++) {
        int o = tid + 256 * i;
        int half = o >= 384;
        int rem = o - half * 384;
        int brow = rem >> 2, grp = rem & 3;
        b_half[i] = half;
        int grow = (brow >> 5) * 256 + j0 + (brow & 31);
        b_src[i] = (size_t)grow * 256 + grp * 8;
        b_dst[i] = 16384 + half * 6144 + SWM(brow, grp);
    }

    auto stage = [&](int c, int buf) {
        uint32_t ab = sbase + buf * K1_STAGE;
        size_t off = aoff + c * 32;
        cpa16(ab + sw0, g_st_h[cur] + off);
        cpa16(ab + sw1, g_st_h[cur] + off + 8);
        cpa16(ab + 8192 + sw0, g_st_l[cur] + off);
        cpa16(ab + 8192 + sw1, g_st_l[cur] + off + 8);
#pragma unroll
        for (int i = 0; i < 3; i++) {
            const __half* src = (b_half[i] ? g_GN_l : g_GN_h) + b_src[i] + c * 32;
            cpa16(ab + b_dst[i], src);
        }
    };

    stage(0, 0);
    asm volatile("cp.async.commit_group;");
    stage(1, 1);
    asm volatile("cp.async.commit_group;");

    if (tid < 128) {
        int grow = rbase + tid;
        int tok_out = 0;
        if (t > 0) {
            float lp;
            int tok = combine_row(grow, &lp);
            int alive = g_alive[(t - 1) & 1][grow];
            tok_out = alive ? tok : 0;
            if (blockIdx.x == 0) {
                if (alive) g_logp[grow] += lp;
                if (alive && tok == 0) g_N[grow] = t;
                g_alive[t & 1][grow] = (alive && tok != 0) ? 1 : 0;
                out[(size_t)grow * NT + (t - 1)] = (float)tok_out;
            }
        }
        tok_sm[tid] = tok_out;
    }

    for (int c = 0; c < 8; c++) {
        if (c < 7) asm volatile("cp.async.wait_group 1;");
        else       asm volatile("cp.async.wait_group 0;");
        __syncthreads();
        if (c < 6) {
            stage(c + 2, (c + 2) % 3);
            asm volatile("cp.async.commit_group;");
        }
        uint32_t ab = sbase + (c % 3) * K1_STAGE;
#pragma unroll
        for (int q = 0; q < 2; q++) {
            int gb = q * 2;
            uint32_t aAddr[2], bAddr[6];
            {
                int rl = wm * 32 + (lane & 15);
                int ga = gb + (lane >> 4);
#pragma unroll
                for (int mt = 0; mt < 2; mt++)
                    aAddr[mt] = ab + SWM(rl + mt * 16, ga);
                int rb0 = wn * 48 + (lane & 7);
                int gbb = gb + ((lane >> 3) & 1);
#pragma unroll
                for (int nt = 0; nt < 6; nt++)
                    bAddr[nt] = ab + 16384 + SWM(rb0 + nt * 8, gbb);
            }
            uint32_t af[2][4], bh[6][2], bl[6][2];
#pragma unroll
            for (int mt = 0; mt < 2; mt++) ldm4(af[mt], aAddr[mt]);
#pragma unroll
            for (int nt = 0; nt < 6; nt++) ldm2(bh[nt], bAddr[nt]);
#pragma unroll
            for (int mt = 0; mt < 2; mt++)
#pragma unroll
                for (int nt = 0; nt < 6; nt++) mma16816(acc[mt][nt], af[mt], bh[nt]);
#pragma unroll
            for (int nt = 0; nt < 6; nt++) ldm2(bl[nt], bAddr[nt] + 6144);
#pragma unroll
            for (int mt = 0; mt < 2; mt++)
#pragma unroll
                for (int nt = 0; nt < 6; nt++) mma16816(acc[mt][nt], af[mt], bl[nt]);
#pragma unroll
            for (int mt = 0; mt < 2; mt++) ldm4(af[mt], aAddr[mt] + 8192);
#pragma unroll
            for (int mt = 0; mt < 2; mt++)
#pragma unroll
                for (int nt = 0; nt < 6; nt++) mma16816(acc[mt][nt], af[mt], bh[nt]);
        }
    }

    float* Cs = (float*)smem;
    __syncthreads();
#pragma unroll
    for (int mt = 0; mt < 2; mt++)
#pragma unroll
        for (int nt = 0; nt < 6; nt++) {
            int r0 = wm * 32 + mt * 16 + (lane >> 2);
            int c0 = wn * 48 + nt * 8 + (lane & 3) * 2;
            Cs[r0 * 100 + c0] = acc[mt][nt][0];
            Cs[r0 * 100 + c0 + 1] = acc[mt][nt][1];
            Cs[(r0 + 8) * 100 + c0] = acc[mt][nt][2];
            Cs[(r0 + 8) * 100 + c0 + 1] = acc[mt][nt][3];
        }
    __syncthreads();
    {
        int jl = tid & 31, rseg = tid >> 5;
        int j = j0 + jl;
        float bhn = bhh[512 + j];
#pragma unroll
        for (int rr = 0; rr < 16; rr++) {
            int r = rseg * 16 + rr;
            int grow = rbase + r;
            int tok = tok_sm[r];
            const float* Trow = g_T + (size_t)tok * 768;
            float cr = Cs[r * 100 + jl] + Trow[j];
            float cz = Cs[r * 100 + 32 + jl] + Trow[256 + j];
            float cn = Cs[r * 100 + 64 + jl] + bhn;
            size_t so = (size_t)grow * 256 + j;
            float hold = __half2float(g_st_h[cur][so]) + __half2float(g_st_l[cur][so]);
            float rg = 1.0f / (1.0f + expf(-cr));
            float zg = 1.0f / (1.0f + expf(-cz));
            float nn = tanhf(Trow[512 + j] + rg * cn);
            float v = (1.0f - zg) * nn + zg * hold;
            __half hh, hl;
            split2(v, hh, hl);
            g_st_h[nxt][so] = hh;
            g_st_l[nxt][so] = hl;
        }
    }
}

// ============ K2: logits GEMM + fused gumbel-argmax partials ============
#define K2_SMEM (3 * 32768)
__global__ void __maxnreg__(120) k2_mma(int t, const float* __restrict__ bout) {
    extern __shared__ char smem[];
    const uint32_t sbase = smem_u32(smem);
    const int tid = threadIdx.x;
    const int lane = tid & 31, wid = tid >> 5;
    const int wm = wid & 1, wn = wid >> 1;
    const int v0 = blockIdx.x * 128;
    const int rbase = blockIdx.y * 128;
    const int nxt = (t + 1) & 1;
    const float* __restrict__ noise = g_noiseAll[t];

    const int arow = tid >> 1, ahalf = tid & 1;
    const uint32_t sw0 = SWM(arow, ahalf * 2);
    const uint32_t sw1 = SWM(arow, ahalf * 2 + 1);

    float acc[4][4][4];
#pragma unroll
    for (int i = 0; i < 4; i++)
#pragma unroll
        for (int j = 0; j < 4; j++)
#pragma unroll
            for (int q = 0; q < 4; q++) acc[i][j][q] = 0.0f;

    auto stage = [&](int c, int buf) {
        uint32_t ab = sbase + buf * 32768;
        size_t off = (size_t)(rbase + arow) * 256 + c * 32 + ahalf * 16;
        cpa16(ab + sw0, g_st_h[nxt] + off);
        cpa16(ab + sw1, g_st_h[nxt] + off + 8);
        cpa16(ab + 8192 + sw0, g_st_l[nxt] + off);
        cpa16(ab + 8192 + sw1, g_st_l[nxt] + off + 8);
        size_t offb = (size_t)(v0 + arow) * 256 + c * 32 + ahalf * 16;
        cpa16(ab + 16384 + sw0, g_Wo_h + offb);
        cpa16(ab + 16384 + sw1, g_Wo_h + offb + 8);
        cpa16(ab + 24576 + sw0, g_Wo_l + offb);
        cpa16(ab + 24576 + sw1, g_Wo_l + offb + 8);
    };

    stage(0, 0);
    asm volatile("cp.async.commit_group;");
    stage(1, 1);
    asm volatile("cp.async.commit_group;");

    for (int c = 0; c < 8; c++) {
        if (c < 7) asm volatile("cp.async.wait_group 1;");
        else       asm volatile("cp.async.wait_group 0;");
        __syncthreads();
        if (c < 6) {
            stage(c + 2, (c + 2) % 3);
            asm volatile("cp.async.commit_group;");
        }
        uint32_t ab = sbase + (c % 3) * 32768;
#pragma unroll
        for (int q = 0; q < 2; q++) {
            int gb = q * 2;
            uint32_t aAddr[4], bAddr[4];
            {
                int rl = wm * 64 + (lane & 15);
                int ga = gb + (lane >> 4);
#pragma unroll
                for (int mt = 0; mt < 4; mt++)
                    aAddr[mt] = ab + SWM(rl + mt * 16, ga);
                int rb = wn * 32 + (lane & 7);
                int gbb = gb + ((lane >> 3) & 1);
#pragma unroll
                for (int nt = 0; nt < 4; nt++)
                    bAddr[nt] = ab + 16384 + SWM(rb + nt * 8, gbb);
            }
            uint32_t af[4][4], bh[4][2], bl[4][2];
#pragma unroll
            for (int mt = 0; mt < 4; mt++) ldm4(af[mt], aAddr[mt]);
#pragma unroll
            for (int nt = 0; nt < 4; nt++) ldm2(bh[nt], bAddr[nt]);
#pragma unroll
            for (int mt = 0; mt < 4; mt++)
#pragma unroll
                for (int nt = 0; nt < 4; nt++) mma16816(acc[mt][nt], af[mt], bh[nt]);
#pragma unroll
            for (int nt = 0; nt < 4; nt++) ldm2(bl[nt], bAddr[nt] + 8192);
#pragma unroll
            for (int mt = 0; mt < 4; mt++)
#pragma unroll
                for (int nt = 0; nt < 4; nt++) mma16816(acc[mt][nt], af[mt], bl[nt]);
#pragma unroll
            for (int mt = 0; mt < 4; mt++) ldm4(af[mt], aAddr[mt] + 8192);
#pragma unroll
            for (int mt = 0; mt < 4; mt++)
#pragma unroll
                for (int nt = 0; nt < 4; nt++) mma16816(acc[mt][nt], af[mt], bh[nt]);
        }
    }

    // ---- epilogue: bias, row-max, gumbel-argmax + sumexp partials ----
#pragma unroll
    for (int nt = 0; nt < 4; nt++) {
        int c0 = v0 + wn * 32 + nt * 8 + (lane & 3) * 2;
        float b0 = bout[c0], b1 = bout[c0 + 1];
#pragma unroll
        for (int mt = 0; mt < 4; mt++) {
            acc[mt][nt][0] += b0; acc[mt][nt][1] += b1;
            acc[mt][nt][2] += b0; acc[mt][nt][3] += b1;
        }
    }
    __syncthreads();
    float* msm = (float*)smem;          // [4][128]
    float* vsm = msm + 512;
    float* xsm = vsm + 512;
    float* ssm = xsm + 512;
    int*   ism = (int*)(ssm + 512);

#pragma unroll
    for (int mt = 0; mt < 4; mt++) {
        float mA = -3.4e38f, mB = -3.4e38f;
#pragma unroll
        for (int nt = 0; nt < 4; nt++) {
            mA = fmaxf(mA, fmaxf(acc[mt][nt][0], acc[mt][nt][1]));
            mB = fmaxf(mB, fmaxf(acc[mt][nt][2], acc[mt][nt][3]));
        }
#pragma unroll
        for (int off = 1; off <= 2; off <<= 1) {
            mA = fmaxf(mA, __shfl_xor_sync(0xffffffffu, mA, off));
            mB = fmaxf(mB, __shfl_xor_sync(0xffffffffu, mB, off));
        }
        if ((lane & 3) == 0) {
            int r0 = wm * 64 + mt * 16 + (lane >> 2);
            msm[wn * 128 + r0] = mA;
            msm[wn * 128 + r0 + 8] = mB;
        }
    }
    __syncthreads();
#pragma unroll
    for (int mt = 0; mt < 4; mt++) {
        int r0 = wm * 64 + mt * 16 + (lane >> 2), r1 = r0 + 8;
        float MA = fmaxf(fmaxf(msm[r0], msm[128 + r0]), fmaxf(msm[256 + r0], msm[384 + r0]));
        float MB = fmaxf(fmaxf(msm[r1], msm[128 + r1]), fmaxf(msm[256 + r1], msm[384 + r1]));
        int growA = rbase + r0, growB = rbase + r1;
        float sA = 0.0f, sB = 0.0f;
        float bvA = -3.4e38f, bvB = -3.4e38f, bxA = 0.0f, bxB = 0.0f;
        int biA = 0, biB = 0;
#pragma unroll
        for (int nt = 0; nt < 4; nt++) {
            int c0 = v0 + wn * 32 + nt * 8 + (lane & 3) * 2;
            float2 nA = *(const float2*)&noise[(size_t)growA * NV + c0];
            float2 nB = *(const float2*)&noise[(size_t)growB * NV + c0];
            float x0 = acc[mt][nt][0], x1 = acc[mt][nt][1];
            float vA0 = x0 + nA.x, vA1 = x1 + nA.y;
            if (vA0 > bvA) { bvA = vA0; biA = c0; bxA = x0; }
            if (vA1 > bvA) { bvA = vA1; biA = c0 + 1; bxA = x1; }
            sA += __expf(x0 - MA) + __expf(x1 - MA);
            float x2 = acc[mt][nt][2], x3 = acc[mt][nt][3];
            float vB0 = x2 + nB.x, vB1 = x3 + nB.y;
            if (vB0 > bvB) { bvB = vB0; biB = c0; bxB = x2; }
            if (vB1 > bvB) { bvB = vB1; biB = c0 + 1; bxB = x3; }
            sB += __expf(x2 - MB) + __expf(x3 - MB);
        }
#pragma unroll
        for (int off = 1; off <= 2; off <<= 1) {
            sA += __shfl_xor_sync(0xffffffffu, sA, off);
            sB += __shfl_xor_sync(0xffffffffu, sB, off);
            float ov = __shfl_xor_sync(0xffffffffu, bvA, off);
            int oi = __shfl_xor_sync(0xffffffffu, biA, off);
            float ox = __shfl_xor_sync(0xffffffffu, bxA, off);
            if (ov > bvA || (ov == bvA && oi < biA)) { bvA = ov; biA = oi; bxA = ox; }
            ov = __shfl_xor_sync(0xffffffffu, bvB, off);
            oi = __shfl_xor_sync(0xffffffffu, biB, off);
            ox = __shfl_xor_sync(0xffffffffu, bxB, off);
            if (ov > bvB || (ov == bvB && oi < biB)) { bvB = ov; biB = oi; bxB = ox; }
        }
        if ((lane & 3) == 0) {
            vsm[wn * 128 + r0] = bvA; ism[wn * 128 + r0] = biA;
            xsm[wn * 128 + r0] = bxA; ssm[wn * 128 + r0] = sA;
            vsm[wn * 128 + r1] = bvB; ism[wn * 128 + r1] = biB;
            xsm[wn * 128 + r1] = bxB; ssm[wn * 128 + r1] = sB;
        }
    }
    __syncthreads();
    if (tid < 128) {
        int r = tid, grow = rbase + r;
        float M = fmaxf(fmaxf(msm[r], msm[128 + r]), fmaxf(msm[256 + r], msm[384 + r]));
        float S = ssm[r] + ssm[128 + r] + ssm[256 + r] + ssm[384 + r];
        float bv = vsm[r]; int bi = ism[r]; float bx = xsm[r];
#pragma unroll
        for (int w = 1; w < 4; w++) {
            float ov = vsm[w * 128 + r]; int oi = ism[w * 128 + r];
            if (ov > bv || (ov == bv && oi < bi)) { bv = ov; bi = oi; bx = xsm[w * 128 + r]; }
        }
        g_partA[grow * 4 + blockIdx.x] = make_float4(bv, __int_as_float(bi), bx, M);
        g_partB[grow * 4 + blockIdx.x] = S;
    }
}

// ---------------- fin: combine step 15 + outputs ----------------
__global__ void fin_kernel(float* __restrict__ out) {
    int b = blockIdx.x * blockDim.x + threadIdx.x;
    if (b < NB) {
        float lp;
        int tok = combine_row(b, &lp);
        int alive = g_alive[1][b];
        int tok_out = alive ? tok : 0;
        float logp = g_logp[b] + (alive ? lp : 0.0f);
        out[(size_t)b * NT + 15] = (float)tok_out;
        out[NB * NT + b] = (float)g_N[b];
        out[NB * NT + NB + b] = logp;
    }
}

extern "C" void kernel_launch(void* const* d_in, const int* in_sizes, int n_in,
                              void* d_out, int out_size) {
    const int* actions = (const int*)d_in[0];
    const float* h1 = (const float*)d_in[2];
    const float* d2e = (const float*)d_in[3];
    const float* Wih = (const float*)d_in[4];
    const float* Whh = (const float*)d_in[5];
    const float* bih = (const float*)d_in[6];
    const float* bhh = (const float*)d_in[7];
    const float* Wout = (const float*)d_in[8];
    const float* bout = (const float*)d_in[9];
    float* out = (float*)d_out;

    static cudaStream_t s_side = nullptr;
    static cudaEvent_t s_evRoot = nullptr;
    static cudaEvent_t s_evN[NT];
    if (!s_side) {
        int loPrio = 0, hiPrio = 0;
        cudaDeviceGetStreamPriorityRange(&loPrio, &hiPrio);
        cudaStreamCreateWithPriority(&s_side, cudaStreamNonBlocking, loPrio);
        cudaEventCreateWithFlags(&s_evRoot, cudaEventDisableTiming);
        for (int t = 0; t < NT; t++)
            cudaEventCreateWithFlags(&s_evN[t], cudaEventDisableTiming);
        cudaFuncSetAttribute(k1_mma, cudaFuncAttributeMaxDynamicSharedMemorySize, K1_SMEM);
        cudaFuncSetAttribute(k2_mma, cudaFuncAttributeMaxDynamicSharedMemorySize, K2_SMEM);
    }

    prep_kernel<<<1024, 256>>>(Wih, Whh, Wout);
    tgemm_kernel<<<64, 256>>>(d2e, bih, bhh);
    init_kernel<<<2048, 256>>>(actions, h1);

    // fork: low-priority side stream; small CTAs co-reside with GEMMs (reg headroom)
    cudaEventRecord(s_evRoot, 0);
    cudaStreamWaitEvent(s_side, s_evRoot, 0);
    for (int t = 0; t < NT; t++) {
        noise_kernel<<<2048, 128, 0, s_side>>>(t);
        cudaEventRecord(s_evN[t], s_side);
    }

    for (int t = 0; t < NT; t++) {
        k1_mma<<<dim3(8, 128), 256, K1_SMEM>>>(t, bhh, out);
        cudaStreamWaitEvent(0, s_evN[t], 0);   // join: noise(t) ready before K2(t)
        k2_mma<<<dim3(4, 128), 256, K2_SMEM>>>(t, bout);
    }
    fin_kernel<<<64, 256>>>(out);
}

// round 16
// speedup vs baseline: 1.0754x; 1.0056x over previous
#include <cuda_runtime.h>
#include <cuda_fp16.h>
#include <cstdint>

#define NB 16384
#define NE 256
#define NV 512
#define NT 16

// ---------------- scratch ----------------
__device__ __half g_st_h[2][NB * NE];
__device__ __half g_st_l[2][NB * NE];
__device__ __half g_GN_h[768 * 256];
__device__ __half g_GN_l[768 * 256];
__device__ __half g_Wo_h[NV * NE];
__device__ __half g_Wo_l[NV * NE];
__device__ float g_WihT[256 * 768];
__device__ float g_T[512 * 768];
__device__ float g_noise[NB * NV];   // per-step scratch: written+read by same K2 thread
__device__ float4 g_partA[NB * 4];   // (bestval, idx-bits, x_best, M) per vblk
__device__ float g_partB[NB * 4];    // sumexp per vblk
__device__ int g_alive[2][NB];
__device__ int g_N[NB];
__device__ float g_logp[NB];
__device__ uint32_t g_keys[NT][2];

#define SWM(row, g) ((((row) * 4) + ((g) ^ ((((row) >> 1)) & 3))) * 16)
#define TINYF 1.17549435e-38f

__device__ __forceinline__ uint32_t smem_u32(const void* p) {
    uint32_t a;
    asm("{ .reg .u64 t; cvta.to.shared.u64 t, %1; cvt.u32.u64 %0, t; }" : "=r"(a) : "l"(p));
    return a;
}
__device__ __forceinline__ void cpa16(uint32_t s, const void* g) {
    asm volatile("cp.async.ca.shared.global [%0], [%1], 16;" :: "r"(s), "l"(g));
}
__device__ __forceinline__ void ldm4(uint32_t* r, uint32_t a) {
    asm volatile("ldmatrix.sync.aligned.m8n8.x4.shared.b16 {%0,%1,%2,%3}, [%4];"
                 : "=r"(r[0]), "=r"(r[1]), "=r"(r[2]), "=r"(r[3]) : "r"(a));
}
__device__ __forceinline__ void ldm2(uint32_t* r, uint32_t a) {
    asm volatile("ldmatrix.sync.aligned.m8n8.x2.shared.b16 {%0,%1}, [%2];"
                 : "=r"(r[0]), "=r"(r[1]) : "r"(a));
}
__device__ __forceinline__ void mma16816(float* c, const uint32_t* a, const uint32_t* b) {
    asm volatile(
        "mma.sync.aligned.m16n8k16.row.col.f32.f16.f16.f32 "
        "{%0,%1,%2,%3}, {%4,%5,%6,%7}, {%8,%9}, {%0,%1,%2,%3};"
        : "+f"(c[0]), "+f"(c[1]), "+f"(c[2]), "+f"(c[3])
        : "r"(a[0]), "r"(a[1]), "r"(a[2]), "r"(a[3]), "r"(b[0]), "r"(b[1]));
}
__device__ __forceinline__ void split2(float v, __half& h, __half& l) {
    h = __float2half(v);
    l = __float2half(v - __half2float(h));
}

// ---------------- threefry ----------------
__device__ __forceinline__ uint32_t rotl32(uint32_t v, int r) {
    return (v << r) | (v >> (32 - r));
}
__device__ __forceinline__ void tfry(uint32_t k0, uint32_t k1,
                                     uint32_t c0, uint32_t c1,
                                     uint32_t& o0, uint32_t& o1) {
    uint32_t k2 = k0 ^ k1 ^ 0x1BD11BDAu;
    uint32_t x0 = c0 + k0, x1 = c1 + k1;
#define R4(a,b,c,d) { x0+=x1; x1=rotl32(x1,a); x1^=x0; x0+=x1; x1=rotl32(x1,b); x1^=x0; \
                      x0+=x1; x1=rotl32(x1,c); x1^=x0; x0+=x1; x1=rotl32(x1,d); x1^=x0; }
    R4(13,15,26,6)  x0 += k1; x1 += k2 + 1u;
    R4(17,29,16,24) x0 += k2; x1 += k0 + 2u;
    R4(13,15,26,6)  x0 += k0; x1 += k1 + 3u;
    R4(17,29,16,24) x0 += k1; x1 += k2 + 4u;
    R4(13,15,26,6)  x0 += k2; x1 += k0 + 5u;
#undef R4
    o0 = x0; o1 = x1;
}

// exact gumbel (bit-identical to proven reference chain)
__device__ __forceinline__ float exact_gumbel(uint32_t k0, uint32_t k1, uint32_t idx) {
    uint32_t o0, o1;
    tfry(k0, k1, 0u, idx, o0, o1);
    uint32_t bits = o0 ^ o1;
    float f = __uint_as_float((bits >> 9) | 0x3f800000u) - 1.0f;
    float u = fmaxf(TINYF, f * (1.0f - TINYF) + TINYF);
    return -logf(-logf(u));
}

__device__ __forceinline__ int combine_row(int grow, float* lp_out) {
    float4 pa[4];
    float sv[4];
#pragma unroll
    for (int i = 0; i < 4; i++) {
        pa[i] = g_partA[grow * 4 + i];
        sv[i] = g_partB[grow * 4 + i];
    }
    float M = fmaxf(fmaxf(pa[0].w, pa[1].w), fmaxf(pa[2].w, pa[3].w));
    float S = 0.0f;
#pragma unroll
    for (int i = 0; i < 4; i++) S += sv[i] * __expf(pa[i].w - M);
    float bv = pa[0].x;
    int bi = __float_as_int(pa[0].y);
    float bx = pa[0].z;
#pragma unroll
    for (int i = 1; i < 4; i++) {
        int oi = __float_as_int(pa[i].y);
        if (pa[i].x > bv || (pa[i].x == bv && oi < bi)) {
            bv = pa[i].x; bi = oi; bx = pa[i].z;
        }
    }
    *lp_out = bx - M - logf(S);
    return bi;
}

// ---------------- prep ----------------
__global__ void prep_kernel(const float* __restrict__ Wih,
                            const float* __restrict__ Whh,
                            const float* __restrict__ Wout) {
    int tid = blockIdx.x * blockDim.x + threadIdx.x;
    int stride = gridDim.x * blockDim.x;
    for (int i = tid; i < 768 * 256; i += stride) {
        __half h, l; split2(Whh[i], h, l);
        g_GN_h[i] = h; g_GN_l[i] = l;
    }
    for (int i = tid; i < 256 * 768; i += stride) {
        int k = i / 768, np = i - k * 768;
        g_WihT[i] = Wih[np * 256 + k];
    }
    for (int i = tid; i < NV * NE; i += stride) {
        __half h, l;
        split2(Wout[i], h, l);
        g_Wo_h[i] = h; g_Wo_l[i] = l;
    }
    if (blockIdx.x == 0 && threadIdx.x == 0) {
        for (int t = 0; t < NT; t++) {
            uint32_t a, b;
            tfry(0u, 42u, 0u, (uint32_t)t, a, b);
            g_keys[t][0] = a; g_keys[t][1] = b;
        }
    }
}

__global__ __launch_bounds__(256)
void tgemm_kernel(const float* __restrict__ d2e,
                  const float* __restrict__ bih,
                  const float* __restrict__ bhh) {
    __shared__ float es[8][256];
    int tokbase = blockIdx.x * 8;
    int tid = threadIdx.x;
    for (int i = tid; i < 8 * 256; i += 256)
        es[i >> 8][i & 255] = d2e[(tokbase + (i >> 8)) * 256 + (i & 255)];
    __syncthreads();
#pragma unroll
    for (int p = 0; p < 3; p++) {
        int np = tid + p * 256;
        float acc[8];
        float bias = bih[np] + (np < 512 ? bhh[np] : 0.0f);
#pragma unroll
        for (int t = 0; t < 8; t++) acc[t] = 0.0f;
        for (int k = 0; k < 256; k++) {
            float w = g_WihT[k * 768 + np];
#pragma unroll
            for (int t = 0; t < 8; t++) acc[t] += es[t][k] * w;
        }
#pragma unroll
        for (int t = 0; t < 8; t++)
            g_T[(tokbase + t) * 768 + np] = acc[t] + bias;
    }
}

__global__ void init_kernel(const int* __restrict__ actions,
                            const float* __restrict__ h1) {
    int tid = blockIdx.x * blockDim.x + threadIdx.x;
    int stride = gridDim.x * blockDim.x;
    for (int i = tid; i < NB * NE; i += stride) {
        int b = i >> 8, e = i & 255;
        float v = h1[actions[b] * NE + e];
        __half h, l; split2(v, h, l);
        g_st_h[0][i] = h; g_st_l[0][i] = l;
    }
    for (int i = tid; i < NB; i += stride) {
        g_alive[0][i] = 1; g_N[i] = NT; g_logp[i] = 0.0f;
    }
}

// ============ K1: combine(t-1) + state @ Whh^T + GRU epilogue ============
#define K1_STAGE 28672
#define K1_SMEM (3 * K1_STAGE + 512)
__global__ __launch_bounds__(256, 2)
void k1_mma(int t, const float* __restrict__ bhh, float* __restrict__ out) {
    extern __shared__ char smem[];
    const uint32_t sbase = smem_u32(smem);
    const int tid = threadIdx.x;
    const int lane = tid & 31, wid = tid >> 5;
    const int wm = wid & 3, wn = wid >> 2;
    const int j0 = blockIdx.x * 32;
    const int rbase = blockIdx.y * 128;
    const int cur = t & 1, nxt = cur ^ 1;
    int* tok_sm = (int*)(smem + 3 * K1_STAGE);

    const int arow = tid >> 1, ahalf = tid & 1;
    const uint32_t sw0 = SWM(arow, ahalf * 2);
    const uint32_t sw1 = SWM(arow, ahalf * 2 + 1);
    const size_t aoff = (size_t)(rbase + arow) * 256 + ahalf * 16;

    float acc[2][6][4];
#pragma unroll
    for (int i = 0; i < 2; i++)
#pragma unroll
        for (int j = 0; j < 6; j++)
#pragma unroll
            for (int q = 0; q < 4; q++) acc[i][j][q] = 0.0f;

    int b_half[3];
    size_t b_src[3];
    uint32_t b_dst[3];
#pragma unroll
    for (int i = 0; i < 3; i++) {
        int o = tid + 256 * i;
        int half = o >= 384;
        int rem = o - half * 384;
        int brow = rem >> 2, grp = rem & 3;
        b_half[i] = half;
        int grow = (brow >> 5) * 256 + j0 + (brow & 31);
        b_src[i] = (size_t)grow * 256 + grp * 8;
        b_dst[i] = 16384 + half * 6144 + SWM(brow, grp);
    }

    auto stage = [&](int c, int buf) {
        uint32_t ab = sbase + buf * K1_STAGE;
        size_t off = aoff + c * 32;
        cpa16(ab + sw0, g_st_h[cur] + off);
        cpa16(ab + sw1, g_st_h[cur] + off + 8);
        cpa16(ab + 8192 + sw0, g_st_l[cur] + off);
        cpa16(ab + 8192 + sw1, g_st_l[cur] + off + 8);
#pragma unroll
        for (int i = 0; i < 3; i++) {
            const __half* src = (b_half[i] ? g_GN_l : g_GN_h) + b_src[i] + c * 32;
            cpa16(ab + b_dst[i], src);
        }
    };

    stage(0, 0);
    asm volatile("cp.async.commit_group;");
    stage(1, 1);
    asm volatile("cp.async.commit_group;");

    if (tid < 128) {
        int grow = rbase + tid;
        int tok_out = 0;
        if (t > 0) {
            float lp;
            int tok = combine_row(grow, &lp);
            int alive = g_alive[(t - 1) & 1][grow];
            tok_out = alive ? tok : 0;
            if (blockIdx.x == 0) {
                if (alive) g_logp[grow] += lp;
                if (alive && tok == 0) g_N[grow] = t;
                g_alive[t & 1][grow] = (alive && tok != 0) ? 1 : 0;
                out[(size_t)grow * NT + (t - 1)] = (float)tok_out;
            }
        }
        tok_sm[tid] = tok_out;
    }

    for (int c = 0; c < 8; c++) {
        if (c < 7) asm volatile("cp.async.wait_group 1;");
        else       asm volatile("cp.async.wait_group 0;");
        __syncthreads();
        if (c < 6) {
            stage(c + 2, (c + 2) % 3);
            asm volatile("cp.async.commit_group;");
        }
        uint32_t ab = sbase + (c % 3) * K1_STAGE;
#pragma unroll
        for (int q = 0; q < 2; q++) {
            int gb = q * 2;
            uint32_t aAddr[2], bAddr[6];
            {
                int rl = wm * 32 + (lane & 15);
                int ga = gb + (lane >> 4);
#pragma unroll
                for (int mt = 0; mt < 2; mt++)
                    aAddr[mt] = ab + SWM(rl + mt * 16, ga);
                int rb0 = wn * 48 + (lane & 7);
                int gbb = gb + ((lane >> 3) & 1);
#pragma unroll
                for (int nt = 0; nt < 6; nt++)
                    bAddr[nt] = ab + 16384 + SWM(rb0 + nt * 8, gbb);
            }
            uint32_t af[2][4], bh[6][2], bl[6][2];
#pragma unroll
            for (int mt = 0; mt < 2; mt++) ldm4(af[mt], aAddr[mt]);
#pragma unroll
            for (int nt = 0; nt < 6; nt++) ldm2(bh[nt], bAddr[nt]);
#pragma unroll
            for (int mt = 0; mt < 2; mt++)
#pragma unroll
                for (int nt = 0; nt < 6; nt++) mma16816(acc[mt][nt], af[mt], bh[nt]);
#pragma unroll
            for (int nt = 0; nt < 6; nt++) ldm2(bl[nt], bAddr[nt] + 6144);
#pragma unroll
            for (int mt = 0; mt < 2; mt++)
#pragma unroll
                for (int nt = 0; nt < 6; nt++) mma16816(acc[mt][nt], af[mt], bl[nt]);
#pragma unroll
            for (int mt = 0; mt < 2; mt++) ldm4(af[mt], aAddr[mt] + 8192);
#pragma unroll
            for (int mt = 0; mt < 2; mt++)
#pragma unroll
                for (int nt = 0; nt < 6; nt++) mma16816(acc[mt][nt], af[mt], bh[nt]);
        }
    }

    float* Cs = (float*)smem;
    __syncthreads();
#pragma unroll
    for (int mt = 0; mt < 2; mt++)
#pragma unroll
        for (int nt = 0; nt < 6; nt++) {
            int r0 = wm * 32 + mt * 16 + (lane >> 2);
            int c0 = wn * 48 + nt * 8 + (lane & 3) * 2;
            Cs[r0 * 100 + c0] = acc[mt][nt][0];
            Cs[r0 * 100 + c0 + 1] = acc[mt][nt][1];
            Cs[(r0 + 8) * 100 + c0] = acc[mt][nt][2];
            Cs[(r0 + 8) * 100 + c0 + 1] = acc[mt][nt][3];
        }
    __syncthreads();
    {
        int jl = tid & 31, rseg = tid >> 5;
        int j = j0 + jl;
        float bhn = bhh[512 + j];
#pragma unroll
        for (int rr = 0; rr < 16; rr++) {
            int r = rseg * 16 + rr;
            int grow = rbase + r;
            int tok = tok_sm[r];
            const float* Trow = g_T + (size_t)tok * 768;
            float cr = Cs[r * 100 + jl] + Trow[j];
            float cz = Cs[r * 100 + 32 + jl] + Trow[256 + j];
            float cn = Cs[r * 100 + 64 + jl] + bhn;
            size_t so = (size_t)grow * 256 + j;
            float hold = __half2float(g_st_h[cur][so]) + __half2float(g_st_l[cur][so]);
            float rg = 1.0f / (1.0f + expf(-cr));
            float zg = 1.0f / (1.0f + expf(-cz));
            float nn = tanhf(Trow[512 + j] + rg * cn);
            float v = (1.0f - zg) * nn + zg * hold;
            __half hh, hl;
            split2(v, hh, hl);
            g_st_h[nxt][so] = hh;
            g_st_l[nxt][so] = hl;
        }
    }
}

// ============ K2: logits GEMM + inline noise gen + fused gumbel-argmax ============
#define K2_SMEM (3 * 32768)
__global__ __launch_bounds__(256, 2)
void k2_mma(int t, const float* __restrict__ bout) {
    extern __shared__ char smem[];
    const uint32_t sbase = smem_u32(smem);
    const int tid = threadIdx.x;
    const int lane = tid & 31, wid = tid >> 5;
    const int wm = wid & 1, wn = wid >> 1;
    const int v0 = blockIdx.x * 128;
    const int rbase = blockIdx.y * 128;
    const int nxt = (t + 1) & 1;
    const uint32_t k0t = g_keys[t][0], k1t = g_keys[t][1];

    const int arow = tid >> 1, ahalf = tid & 1;
    const uint32_t sw0 = SWM(arow, ahalf * 2);
    const uint32_t sw1 = SWM(arow, ahalf * 2 + 1);

    float acc[4][4][4];
#pragma unroll
    for (int i = 0; i < 4; i++)
#pragma unroll
        for (int j = 0; j < 4; j++)
#pragma unroll
            for (int q = 0; q < 4; q++) acc[i][j][q] = 0.0f;

    auto stage = [&](int c, int buf) {
        uint32_t ab = sbase + buf * 32768;
        size_t off = (size_t)(rbase + arow) * 256 + c * 32 + ahalf * 16;
        cpa16(ab + sw0, g_st_h[nxt] + off);
        cpa16(ab + sw1, g_st_h[nxt] + off + 8);
        cpa16(ab + 8192 + sw0, g_st_l[nxt] + off);
        cpa16(ab + 8192 + sw1, g_st_l[nxt] + off + 8);
        size_t offb = (size_t)(v0 + arow) * 256 + c * 32 + ahalf * 16;
        cpa16(ab + 16384 + sw0, g_Wo_h + offb);
        cpa16(ab + 16384 + sw1, g_Wo_h + offb + 8);
        cpa16(ab + 24576 + sw0, g_Wo_l + offb);
        cpa16(ab + 24576 + sw1, g_Wo_l + offb + 8);
    };

    stage(0, 0);
    asm volatile("cp.async.commit_group;");
    stage(1, 1);
    asm volatile("cp.async.commit_group;");

    for (int c = 0; c < 8; c++) {
        if (c < 7) asm volatile("cp.async.wait_group 1;");
        else       asm volatile("cp.async.wait_group 0;");
        __syncthreads();
        if (c < 6) {
            stage(c + 2, (c + 2) % 3);
            asm volatile("cp.async.commit_group;");
        }
        uint32_t ab = sbase + (c % 3) * 32768;
#pragma unroll
        for (int q = 0; q < 2; q++) {
            int gb = q * 2;
            uint32_t aAddr[4], bAddr[4];
            {
                int rl = wm * 64 + (lane & 15);
                int ga = gb + (lane >> 4);
#pragma unroll
                for (int mt = 0; mt < 4; mt++)
                    aAddr[mt] = ab + SWM(rl + mt * 16, ga);
                int rb = wn * 32 + (lane & 7);
                int gbb = gb + ((lane >> 3) & 1);
#pragma unroll
                for (int nt = 0; nt < 4; nt++)
                    bAddr[nt] = ab + 16384 + SWM(rb + nt * 8, gbb);
            }
            uint32_t af[4][4], bh[4][2], bl[4][2];
#pragma unroll
            for (int mt = 0; mt < 4; mt++) ldm4(af[mt], aAddr[mt]);
#pragma unroll
            for (int nt = 0; nt < 4; nt++) ldm2(bh[nt], bAddr[nt]);
#pragma unroll
            for (int mt = 0; mt < 4; mt++)
#pragma unroll
                for (int nt = 0; nt < 4; nt++) mma16816(acc[mt][nt], af[mt], bh[nt]);
#pragma unroll
            for (int nt = 0; nt < 4; nt++) ldm2(bl[nt], bAddr[nt] + 8192);
#pragma unroll
            for (int mt = 0; mt < 4; mt++)
#pragma unroll
                for (int nt = 0; nt < 4; nt++) mma16816(acc[mt][nt], af[mt], bl[nt]);
#pragma unroll
            for (int mt = 0; mt < 4; mt++) ldm4(af[mt], aAddr[mt] + 8192);
#pragma unroll
            for (int mt = 0; mt < 4; mt++)
#pragma unroll
                for (int nt = 0; nt < 4; nt++) mma16816(acc[mt][nt], af[mt], bh[nt]);
        }
        // ---- inline noise gen: this thread's epilogue values for (mt=c>>1, half=c&1)
        {
            int mtc = c >> 1;
            int rc = wm * 64 + mtc * 16 + (lane >> 2) + (c & 1) * 8;
            int growc = rbase + rc;
#pragma unroll
            for (int nt = 0; nt < 4; nt++) {
                int c0 = v0 + wn * 32 + nt * 8 + (lane & 3) * 2;
                uint32_t idx = (uint32_t)(growc * NV + c0);
                float g0 = exact_gumbel(k0t, k1t, idx);
                float g1 = exact_gumbel(k0t, k1t, idx + 1);
                *(float2*)&g_noise[(size_t)growc * NV + c0] = make_float2(g0, g1);
            }
        }
    }

    // ---- epilogue: bias, row-max, gumbel-argmax + sumexp partials ----
#pragma unroll
    for (int nt = 0; nt < 4; nt++) {
        int c0 = v0 + wn * 32 + nt * 8 + (lane & 3) * 2;
        float b0 = bout[c0], b1 = bout[c0 + 1];
#pragma unroll
        for (int mt = 0; mt < 4; mt++) {
            acc[mt][nt][0] += b0; acc[mt][nt][1] += b1;
            acc[mt][nt][2] += b0; acc[mt][nt][3] += b1;
        }
    }
    __syncthreads();
    float* msm = (float*)smem;          // [4][128]
    float* vsm = msm + 512;
    float* xsm = vsm + 512;
    float* ssm = xsm + 512;
    int*   ism = (int*)(ssm + 512);

#pragma unroll
    for (int mt = 0; mt < 4; mt++) {
        float mA = -3.4e38f, mB = -3.4e38f;
#pragma unroll
        for (int nt = 0; nt < 4; nt++) {
            mA = fmaxf(mA, fmaxf(acc[mt][nt][0], acc[mt][nt][1]));
            mB = fmaxf(mB, fmaxf(acc[mt][nt][2], acc[mt][nt][3]));
        }
#pragma unroll
        for (int off = 1; off <= 2; off <<= 1) {
            mA = fmaxf(mA, __shfl_xor_sync(0xffffffffu, mA, off));
            mB = fmaxf(mB, __shfl_xor_sync(0xffffffffu, mB, off));
        }
        if ((lane & 3) == 0) {
            int r0 = wm * 64 + mt * 16 + (lane >> 2);
            msm[wn * 128 + r0] = mA;
            msm[wn * 128 + r0 + 8] = mB;
        }
    }
    __syncthreads();
#pragma unroll
    for (int mt = 0; mt < 4; mt++) {
        int r0 = wm * 64 + mt * 16 + (lane >> 2), r1 = r0 + 8;
        float MA = fmaxf(fmaxf(msm[r0], msm[128 + r0]), fmaxf(msm[256 + r0], msm[384 + r0]));
        float MB = fmaxf(fmaxf(msm[r1], msm[128 + r1]), fmaxf(msm[256 + r1], msm[384 + r1]));
        int growA = rbase + r0, growB = rbase + r1;
        float sA = 0.0f, sB = 0.0f;
        float bvA = -3.4e38f, bvB = -3.4e38f, bxA = 0.0f, bxB = 0.0f;
        int biA = 0, biB = 0;
#pragma unroll
        for (int nt = 0; nt < 4; nt++) {
            int c0 = v0 + wn * 32 + nt * 8 + (lane & 3) * 2;
            float2 nA = *(const float2*)&g_noise[(size_t)growA * NV + c0];
            float2 nB = *(const float2*)&g_noise[(size_t)growB * NV + c0];
            float x0 = acc[mt][nt][0], x1 = acc[mt][nt][1];
            float vA0 = x0 + nA.x, vA1 = x1 + nA.y;
            if (vA0 > bvA) { bvA = vA0; biA = c0; bxA = x0; }
            if (vA1 > bvA) { bvA = vA1; biA = c0 + 1; bxA = x1; }
            sA += __expf(x0 - MA) + __expf(x1 - MA);
            float x2 = acc[mt][nt][2], x3 = acc[mt][nt][3];
            float vB0 = x2 + nB.x, vB1 = x3 + nB.y;
            if (vB0 > bvB) { bvB = vB0; biB = c0; bxB = x2; }
            if (vB1 > bvB) { bvB = vB1; biB = c0 + 1; bxB = x3; }
            sB += __expf(x2 - MB) + __expf(x3 - MB);
        }
#pragma unroll
        for (int off = 1; off <= 2; off <<= 1) {
            sA += __shfl_xor_sync(0xffffffffu, sA, off);
            sB += __shfl_xor_sync(0xffffffffu, sB, off);
            float ov = __shfl_xor_sync(0xffffffffu, bvA, off);
            int oi = __shfl_xor_sync(0xffffffffu, biA, off);
            float ox = __shfl_xor_sync(0xffffffffu, bxA, off);
            if (ov > bvA || (ov == bvA && oi < biA)) { bvA = ov; biA = oi; bxA = ox; }
            ov = __shfl_xor_sync(0xffffffffu, bvB, off);
            oi = __shfl_xor_sync(0xffffffffu, biB, off);
            ox = __shfl_xor_sync(0xffffffffu, bxB, off);
            if (ov > bvB || (ov == bvB && oi < biB)) { bvB = ov; biB = oi; bxB = ox; }
        }
        if ((lane & 3) == 0) {
            vsm[wn * 128 + r0] = bvA; ism[wn * 128 + r0] = biA;
            xsm[wn * 128 + r0] = bxA; ssm[wn * 128 + r0] = sA;
            vsm[wn * 128 + r1] = bvB; ism[wn * 128 + r1] = biB;
            xsm[wn * 128 + r1] = bxB; ssm[wn * 128 + r1] = sB;
        }
    }
    __syncthreads();
    if (tid < 128) {
        int r = tid, grow = rbase + r;
        float M = fmaxf(fmaxf(msm[r], msm[128 + r]), fmaxf(msm[256 + r], msm[384 + r]));
        float S = ssm[r] + ssm[128 + r] + ssm[256 + r] + ssm[384 + r];
        float bv = vsm[r]; int bi = ism[r]; float bx = xsm[r];
#pragma unroll
        for (int w = 1; w < 4; w++) {
            float ov = vsm[w * 128 + r]; int oi = ism[w * 128 + r];
            if (ov > bv || (ov == bv && oi < bi)) { bv = ov; bi = oi; bx = xsm[w * 128 + r]; }
        }
        g_partA[grow * 4 + blockIdx.x] = make_float4(bv, __int_as_float(bi), bx, M);
        g_partB[grow * 4 + blockIdx.x] = S;
    }
}

// ---------------- fin: combine step 15 + outputs ----------------
__global__ void fin_kernel(float* __restrict__ out) {
    int b = blockIdx.x * blockDim.x + threadIdx.x;
    if (b < NB) {
        float lp;
        int tok = combine_row(b, &lp);
        int alive = g_alive[1][b];
        int tok_out = alive ? tok : 0;
        float logp = g_logp[b] + (alive ? lp : 0.0f);
        out[(size_t)b * NT + 15] = (float)tok_out;
        out[NB * NT + b] = (float)g_N[b];
        out[NB * NT + NB + b] = logp;
    }
}

extern "C" void kernel_launch(void* const* d_in, const int* in_sizes, int n_in,
                              void* d_out, int out_size) {
    const int* actions = (const int*)d_in[0];
    const float* h1 = (const float*)d_in[2];
    const float* d2e = (const float*)d_in[3];
    const float* Wih = (const float*)d_in[4];
    const float* Whh = (const float*)d_in[5];
    const float* bih = (const float*)d_in[6];
    const float* bhh = (const float*)d_in[7];
    const float* Wout = (const float*)d_in[8];
    const float* bout = (const float*)d_in[9];
    float* out = (float*)d_out;

    cudaFuncSetAttribute(k1_mma, cudaFuncAttributeMaxDynamicSharedMemorySize, K1_SMEM);
    cudaFuncSetAttribute(k2_mma, cudaFuncAttributeMaxDynamicSharedMemorySize, K2_SMEM);

    prep_kernel<<<1024, 256>>>(Wih, Whh, Wout);
    tgemm_kernel<<<64, 256>>>(d2e, bih, bhh);
    init_kernel<<<2048, 256>>>(actions, h1);

    for (int t = 0; t < NT; t++) {
        k1_mma<<<dim3(8, 128), 256, K1_SMEM>>>(t, bhh, out);
        k2_mma<<<dim3(4, 128), 256, K2_SMEM>>>(t, bout);
    }
    fin_kernel<<<64, 256>>>(out);
}

// round 17
// speedup vs baseline: 1.1610x; 1.0797x over previous
#include <cuda_runtime.h>
#include <cuda_fp16.h>
#include <cstdint>

#define NB 16384
#define NE 256
#define NV 512
#define NT 16

// ---------------- scratch ----------------
__device__ __half g_st_h[2][NB * NE];
__device__ __half g_st_l[2][NB * NE];
__device__ __half g_GN_h[768 * 256];
__device__ __half g_GN_l[768 * 256];
__device__ __half g_Wo_h[NV * NE];
__device__ __half g_Wo_l[NV * NE];
__device__ float g_WihT[256 * 768];
__device__ float g_T[512 * 768];
__device__ float g_noiseAll[NT][NB * NV];   // EXACT gumbel noise (side stream)
__device__ float4 g_partA[NB * 4];          // (bestval, idx-bits, x_best, M) per vblk
__device__ float g_partB[NB * 4];           // sumexp per vblk
__device__ int g_alive[2][NB];
__device__ int g_N[NB];
__device__ float g_logp[NB];
__device__ uint32_t g_keys[NT][2];

#define SWM(row, g) ((((row) * 4) + ((g) ^ ((((row) >> 1)) & 3))) * 16)
#define TINYF 1.17549435e-38f

__device__ __forceinline__ uint32_t smem_u32(const void* p) {
    uint32_t a;
    asm("{ .reg .u64 t; cvta.to.shared.u64 t, %1; cvt.u32.u64 %0, t; }" : "=r"(a) : "l"(p));
    return a;
}
__device__ __forceinline__ void cpa16(uint32_t s, const void* g) {
    asm volatile("cp.async.ca.shared.global [%0], [%1], 16;" :: "r"(s), "l"(g));
}
__device__ __forceinline__ void ldm4(uint32_t* r, uint32_t a) {
    asm volatile("ldmatrix.sync.aligned.m8n8.x4.shared.b16 {%0,%1,%2,%3}, [%4];"
                 : "=r"(r[0]), "=r"(r[1]), "=r"(r[2]), "=r"(r[3]) : "r"(a));
}
__device__ __forceinline__ void ldm2(uint32_t* r, uint32_t a) {
    asm volatile("ldmatrix.sync.aligned.m8n8.x2.shared.b16 {%0,%1}, [%2];"
                 : "=r"(r[0]), "=r"(r[1]) : "r"(a));
}
__device__ __forceinline__ void mma16816(float* c, const uint32_t* a, const uint32_t* b) {
    asm volatile(
        "mma.sync.aligned.m16n8k16.row.col.f32.f16.f16.f32 "
        "{%0,%1,%2,%3}, {%4,%5,%6,%7}, {%8,%9}, {%0,%1,%2,%3};"
        : "+f"(c[0]), "+f"(c[1]), "+f"(c[2]), "+f"(c[3])
        : "r"(a[0]), "r"(a[1]), "r"(a[2]), "r"(a[3]), "r"(b[0]), "r"(b[1]));
}
__device__ __forceinline__ void split2(float v, __half& h, __half& l) {
    h = __float2half(v);
    l = __float2half(v - __half2float(h));
}

// ---------------- threefry ----------------
__device__ __forceinline__ uint32_t rotl32(uint32_t v, int r) {
    return (v << r) | (v >> (32 - r));
}
__device__ __forceinline__ void tfry(uint32_t k0, uint32_t k1,
                                     uint32_t c0, uint32_t c1,
                                     uint32_t& o0, uint32_t& o1) {
    uint32_t k2 = k0 ^ k1 ^ 0x1BD11BDAu;
    uint32_t x0 = c0 + k0, x1 = c1 + k1;
#define R4(a,b,c,d) { x0+=x1; x1=rotl32(x1,a); x1^=x0; x0+=x1; x1=rotl32(x1,b); x1^=x0; \
                      x0+=x1; x1=rotl32(x1,c); x1^=x0; x0+=x1; x1=rotl32(x1,d); x1^=x0; }
    R4(13,15,26,6)  x0 += k1; x1 += k2 + 1u;
    R4(17,29,16,24) x0 += k2; x1 += k0 + 2u;
    R4(13,15,26,6)  x0 += k0; x1 += k1 + 3u;
    R4(17,29,16,24) x0 += k1; x1 += k2 + 4u;
    R4(13,15,26,6)  x0 += k2; x1 += k0 + 5u;
#undef R4
    o0 = x0; o1 = x1;
}

__device__ __forceinline__ int combine_row(int grow, float* lp_out) {
    float4 pa[4];
    float sv[4];
#pragma unroll
    for (int i = 0; i < 4; i++) {
        pa[i] = g_partA[grow * 4 + i];
        sv[i] = g_partB[grow * 4 + i];
    }
    float M = fmaxf(fmaxf(pa[0].w, pa[1].w), fmaxf(pa[2].w, pa[3].w));
    float S = 0.0f;
#pragma unroll
    for (int i = 0; i < 4; i++) S += sv[i] * __expf(pa[i].w - M);
    float bv = pa[0].x;
    int bi = __float_as_int(pa[0].y);
    float bx = pa[0].z;
#pragma unroll
    for (int i = 1; i < 4; i++) {
        int oi = __float_as_int(pa[i].y);
        if (pa[i].x > bv || (pa[i].x == bv && oi < bi)) {
            bv = pa[i].x; bi = oi; bx = pa[i].z;
        }
    }
    *lp_out = bx - M - logf(S);
    return bi;
}

// ---------------- noise: EXACT gumbel for one step (side stream) ----------------
__global__ __launch_bounds__(256)
void noise_kernel(int t) {
    const uint32_t k0 = g_keys[t][0], k1 = g_keys[t][1];
    int i = blockIdx.x * blockDim.x + threadIdx.x;
    uint32_t base = (uint32_t)i * 4;
    float r[4];
#pragma unroll
    for (int q = 0; q < 4; q++) {
        uint32_t o0, o1;
        tfry(k0, k1, 0u, base + q, o0, o1);
        uint32_t bits = o0 ^ o1;
        float f = __uint_as_float((bits >> 9) | 0x3f800000u) - 1.0f;
        float u = fmaxf(TINYF, f * (1.0f - TINYF) + TINYF);
        r[q] = -logf(-logf(u));
    }
    *(float4*)&g_noiseAll[t][base] = make_float4(r[0], r[1], r[2], r[3]);
}

// ---------------- prep ----------------
__global__ void prep_kernel(const float* __restrict__ Wih,
                            const float* __restrict__ Whh,
                            const float* __restrict__ Wout) {
    int tid = blockIdx.x * blockDim.x + threadIdx.x;
    int stride = gridDim.x * blockDim.x;
    for (int i = tid; i < 768 * 256; i += stride) {
        __half h, l; split2(Whh[i], h, l);
        g_GN_h[i] = h; g_GN_l[i] = l;
    }
    for (int i = tid; i < 256 * 768; i += stride) {
        int k = i / 768, np = i - k * 768;
        g_WihT[i] = Wih[np * 256 + k];
    }
    for (int i = tid; i < NV * NE; i += stride) {
        __half h, l;
        split2(Wout[i], h, l);
        g_Wo_h[i] = h; g_Wo_l[i] = l;
    }
    if (blockIdx.x == 0 && threadIdx.x == 0) {
        for (int t = 0; t < NT; t++) {
            uint32_t a, b;
            tfry(0u, 42u, 0u, (uint32_t)t, a, b);
            g_keys[t][0] = a; g_keys[t][1] = b;
        }
    }
}

__global__ __launch_bounds__(256)
void tgemm_kernel(const float* __restrict__ d2e,
                  const float* __restrict__ bih,
                  const float* __restrict__ bhh) {
    __shared__ float es[8][256];
    int tokbase = blockIdx.x * 8;
    int tid = threadIdx.x;
    for (int i = tid; i < 8 * 256; i += 256)
        es[i >> 8][i & 255] = d2e[(tokbase + (i >> 8)) * 256 + (i & 255)];
    __syncthreads();
#pragma unroll
    for (int p = 0; p < 3; p++) {
        int np = tid + p * 256;
        float acc[8];
        float bias = bih[np] + (np < 512 ? bhh[np] : 0.0f);
#pragma unroll
        for (int t = 0; t < 8; t++) acc[t] = 0.0f;
        for (int k = 0; k < 256; k++) {
            float w = g_WihT[k * 768 + np];
#pragma unroll
            for (int t = 0; t < 8; t++) acc[t] += es[t][k] * w;
        }
#pragma unroll
        for (int t = 0; t < 8; t++)
            g_T[(tokbase + t) * 768 + np] = acc[t] + bias;
    }
}

__global__ void init_kernel(const int* __restrict__ actions,
                            const float* __restrict__ h1) {
    int tid = blockIdx.x * blockDim.x + threadIdx.x;
    int stride = gridDim.x * blockDim.x;
    for (int i = tid; i < NB * NE; i += stride) {
        int b = i >> 8, e = i & 255;
        float v = h1[actions[b] * NE + e];
        __half h, l; split2(v, h, l);
        g_st_h[0][i] = h; g_st_l[0][i] = l;
    }
    for (int i = tid; i < NB; i += stride) {
        g_alive[0][i] = 1; g_N[i] = NT; g_logp[i] = 0.0f;
    }
}

// ============ K1: 64x96 tile, 3 CTAs/SM. combine(t-1) + state@Whh^T + GRU ============
// smem: [3 stages x 20480B: A_h 4K | A_l 4K | B_h 6K | B_l 6K] + tok_sm
#define K1_STAGE 20480
#define K1_SMEM (3 * K1_STAGE + 256)
__global__ __launch_bounds__(256, 3)
void k1_mma(int t, const float* __restrict__ bhh, float* __restrict__ out) {
    extern __shared__ char smem[];
    const uint32_t sbase = smem_u32(smem);
    const int tid = threadIdx.x;
    const int lane = tid & 31, wid = tid >> 5;
    const int wm = wid & 1, wn = wid >> 1;        // 2 m-blocks x 4 n-blocks (32x24 warp)
    const int j0 = blockIdx.x * 32;
    const int rbase = blockIdx.y * 64;
    const int cur = t & 1, nxt = cur ^ 1;
    int* tok_sm = (int*)(smem + 3 * K1_STAGE);

    // A staging: thread -> (row, grp); 2 cpa16 (h,l)
    const int arow = tid >> 2, agrp = tid & 3;
    const uint32_t aswz = SWM(arow, agrp);
    const size_t aoff = (size_t)(rbase + arow) * 256 + agrp * 8;

    float acc[2][3][4];
#pragma unroll
    for (int i = 0; i < 2; i++)
#pragma unroll
        for (int j = 0; j < 3; j++)
#pragma unroll
            for (int q = 0; q < 4; q++) acc[i][j][q] = 0.0f;

    // B staging: 3 uint4 per thread
    int b_half[3];
    size_t b_src[3];
    uint32_t b_dst[3];
#pragma unroll
    for (int i = 0; i < 3; i++) {
        int o = tid + 256 * i;
        int half = o >= 384;
        int rem = o - half * 384;
        int brow = rem >> 2, grp = rem & 3;
        b_half[i] = half;
        int grow = (brow >> 5) * 256 + j0 + (brow & 31);
        b_src[i] = (size_t)grow * 256 + grp * 8;
        b_dst[i] = 8192 + half * 6144 + SWM(brow, grp);
    }

    auto stage = [&](int c, int buf) {
        uint32_t ab = sbase + buf * K1_STAGE;
        size_t off = aoff + c * 32;
        cpa16(ab + aswz, g_st_h[cur] + off);
        cpa16(ab + 4096 + aswz, g_st_l[cur] + off);
#pragma unroll
        for (int i = 0; i < 3; i++) {
            const __half* src = (b_half[i] ? g_GN_l : g_GN_h) + b_src[i] + c * 32;
            cpa16(ab + b_dst[i], src);
        }
    };

    stage(0, 0);
    asm volatile("cp.async.commit_group;");
    stage(1, 1);
    asm volatile("cp.async.commit_group;");

    // prologue: combine step t-1 partials -> token (+ bookkeeping on jblk0)
    if (tid < 64) {
        int grow = rbase + tid;
        int tok_out = 0;
        if (t > 0) {
            float lp;
            int tok = combine_row(grow, &lp);
            int alive = g_alive[(t - 1) & 1][grow];
            tok_out = alive ? tok : 0;
            if (blockIdx.x == 0) {
                if (alive) g_logp[grow] += lp;
                if (alive && tok == 0) g_N[grow] = t;
                g_alive[t & 1][grow] = (alive && tok != 0) ? 1 : 0;
                out[(size_t)grow * NT + (t - 1)] = (float)tok_out;
            }
        }
        tok_sm[tid] = tok_out;
    }

    for (int c = 0; c < 8; c++) {
        if (c < 7) asm volatile("cp.async.wait_group 1;");
        else       asm volatile("cp.async.wait_group 0;");
        __syncthreads();
        if (c < 6) {
            stage(c + 2, (c + 2) % 3);
            asm volatile("cp.async.commit_group;");
        }
        uint32_t ab = sbase + (c % 3) * K1_STAGE;
#pragma unroll
        for (int q = 0; q < 2; q++) {
            int gb = q * 2;
            uint32_t aAddr[2], bAddr[3];
            {
                int rl = wm * 32 + (lane & 15);
                int ga = gb + (lane >> 4);
#pragma unroll
                for (int mt = 0; mt < 2; mt++)
                    aAddr[mt] = ab + SWM(rl + mt * 16, ga);
                int rb0 = wn * 24 + (lane & 7);
                int gbb = gb + ((lane >> 3) & 1);
#pragma unroll
                for (int nt = 0; nt < 3; nt++)
                    bAddr[nt] = ab + 8192 + SWM(rb0 + nt * 8, gbb);
            }
            uint32_t af[2][4], bh[3][2], bl[3][2];
#pragma unroll
            for (int mt = 0; mt < 2; mt++) ldm4(af[mt], aAddr[mt]);
#pragma unroll
            for (int nt = 0; nt < 3; nt++) ldm2(bh[nt], bAddr[nt]);
#pragma unroll
            for (int mt = 0; mt < 2; mt++)
#pragma unroll
                for (int nt = 0; nt < 3; nt++) mma16816(acc[mt][nt], af[mt], bh[nt]);
#pragma unroll
            for (int nt = 0; nt < 3; nt++) ldm2(bl[nt], bAddr[nt] + 6144);
#pragma unroll
            for (int mt = 0; mt < 2; mt++)
#pragma unroll
                for (int nt = 0; nt < 3; nt++) mma16816(acc[mt][nt], af[mt], bl[nt]);
#pragma unroll
            for (int mt = 0; mt < 2; mt++) ldm4(af[mt], aAddr[mt] + 4096);
#pragma unroll
            for (int mt = 0; mt < 2; mt++)
#pragma unroll
                for (int nt = 0; nt < 3; nt++) mma16816(acc[mt][nt], af[mt], bh[nt]);
        }
    }

    // epilogue: dump C [64][100], token-table GRU, split-store state
    float* Cs = (float*)smem;
    __syncthreads();
#pragma unroll
    for (int mt = 0; mt < 2; mt++)
#pragma unroll
        for (int nt = 0; nt < 3; nt++) {
            int r0 = wm * 32 + mt * 16 + (lane >> 2);
            int c0 = wn * 24 + nt * 8 + (lane & 3) * 2;
            Cs[r0 * 100 + c0] = acc[mt][nt][0];
            Cs[r0 * 100 + c0 + 1] = acc[mt][nt][1];
            Cs[(r0 + 8) * 100 + c0] = acc[mt][nt][2];
            Cs[(r0 + 8) * 100 + c0 + 1] = acc[mt][nt][3];
        }
    __syncthreads();
    {
        int jl = tid & 31, rseg = tid >> 5;
        int j = j0 + jl;
        float bhn = bhh[512 + j];
#pragma unroll
        for (int rr = 0; rr < 8; rr++) {
            int r = rseg * 8 + rr;
            int grow = rbase + r;
            int tok = tok_sm[r];
            const float* Trow = g_T + (size_t)tok * 768;
            float cr = Cs[r * 100 + jl] + Trow[j];
            float cz = Cs[r * 100 + 32 + jl] + Trow[256 + j];
            float cn = Cs[r * 100 + 64 + jl] + bhn;
            size_t so = (size_t)grow * 256 + j;
            float hold = __half2float(g_st_h[cur][so]) + __half2float(g_st_l[cur][so]);
            float rg = 1.0f / (1.0f + expf(-cr));
            float zg = 1.0f / (1.0f + expf(-cz));
            float nn = tanhf(Trow[512 + j] + rg * cn);
            float v = (1.0f - zg) * nn + zg * hold;
            __half hh, hl;
            split2(v, hh, hl);
            g_st_h[nxt][so] = hh;
            g_st_l[nxt][so] = hl;
        }
    }
}

// ============ K2: logits GEMM + fused gumbel-argmax partials ============
#define K2_SMEM (3 * 32768)
__global__ __launch_bounds__(256, 2)
void k2_mma(int t, const float* __restrict__ bout) {
    extern __shared__ char smem[];
    const uint32_t sbase = smem_u32(smem);
    const int tid = threadIdx.x;
    const int lane = tid & 31, wid = tid >> 5;
    const int wm = wid & 1, wn = wid >> 1;
    const int v0 = blockIdx.x * 128;
    const int rbase = blockIdx.y * 128;
    const int nxt = (t + 1) & 1;
    const float* __restrict__ noise = g_noiseAll[t];

    const int arow = tid >> 1, ahalf = tid & 1;
    const uint32_t sw0 = SWM(arow, ahalf * 2);
    const uint32_t sw1 = SWM(arow, ahalf * 2 + 1);

    float acc[4][4][4];
#pragma unroll
    for (int i = 0; i < 4; i++)
#pragma unroll
        for (int j = 0; j < 4; j++)
#pragma unroll
            for (int q = 0; q < 4; q++) acc[i][j][q] = 0.0f;

    auto stage = [&](int c, int buf) {
        uint32_t ab = sbase + buf * 32768;
        size_t off = (size_t)(rbase + arow) * 256 + c * 32 + ahalf * 16;
        cpa16(ab + sw0, g_st_h[nxt] + off);
        cpa16(ab + sw1, g_st_h[nxt] + off + 8);
        cpa16(ab + 8192 + sw0, g_st_l[nxt] + off);
        cpa16(ab + 8192 + sw1, g_st_l[nxt] + off + 8);
        size_t offb = (size_t)(v0 + arow) * 256 + c * 32 + ahalf * 16;
        cpa16(ab + 16384 + sw0, g_Wo_h + offb);
        cpa16(ab + 16384 + sw1, g_Wo_h + offb + 8);
        cpa16(ab + 24576 + sw0, g_Wo_l + offb);
        cpa16(ab + 24576 + sw1, g_Wo_l + offb + 8);
    };

    stage(0, 0);
    asm volatile("cp.async.commit_group;");
    stage(1, 1);
    asm volatile("cp.async.commit_group;");

    for (int c = 0; c < 8; c++) {
        if (c < 7) asm volatile("cp.async.wait_group 1;");
        else       asm volatile("cp.async.wait_group 0;");
        __syncthreads();
        if (c < 6) {
            stage(c + 2, (c + 2) % 3);
            asm volatile("cp.async.commit_group;");
        }
        uint32_t ab = sbase + (c % 3) * 32768;
#pragma unroll
        for (int q = 0; q < 2; q++) {
            int gb = q * 2;
            uint32_t aAddr[4], bAddr[4];
            {
                int rl = wm * 64 + (lane & 15);
                int ga = gb + (lane >> 4);
#pragma unroll
                for (int mt = 0; mt < 4; mt++)
                    aAddr[mt] = ab + SWM(rl + mt * 16, ga);
                int rb = wn * 32 + (lane & 7);
                int gbb = gb + ((lane >> 3) & 1);
#pragma unroll
                for (int nt = 0; nt < 4; nt++)
                    bAddr[nt] = ab + 16384 + SWM(rb + nt * 8, gbb);
            }
            uint32_t af[4][4], bh[4][2], bl[4][2];
#pragma unroll
            for (int mt = 0; mt < 4; mt++) ldm4(af[mt], aAddr[mt]);
#pragma unroll
            for (int nt = 0; nt < 4; nt++) ldm2(bh[nt], bAddr[nt]);
#pragma unroll
            for (int mt = 0; mt < 4; mt++)
#pragma unroll
                for (int nt = 0; nt < 4; nt++) mma16816(acc[mt][nt], af[mt], bh[nt]);
#pragma unroll
            for (int nt = 0; nt < 4; nt++) ldm2(bl[nt], bAddr[nt] + 8192);
#pragma unroll
            for (int mt = 0; mt < 4; mt++)
#pragma unroll
                for (int nt = 0; nt < 4; nt++) mma16816(acc[mt][nt], af[mt], bl[nt]);
#pragma unroll
            for (int mt = 0; mt < 4; mt++) ldm4(af[mt], aAddr[mt] + 8192);
#pragma unroll
            for (int mt = 0; mt < 4; mt++)
#pragma unroll
                for (int nt = 0; nt < 4; nt++) mma16816(acc[mt][nt], af[mt], bh[nt]);
        }
    }

    // ---- epilogue: bias, row-max, gumbel-argmax + sumexp partials ----
#pragma unroll
    for (int nt = 0; nt < 4; nt++) {
        int c0 = v0 + wn * 32 + nt * 8 + (lane & 3) * 2;
        float b0 = bout[c0], b1 = bout[c0 + 1];
#pragma unroll
        for (int mt = 0; mt < 4; mt++) {
            acc[mt][nt][0] += b0; acc[mt][nt][1] += b1;
            acc[mt][nt][2] += b0; acc[mt][nt][3] += b1;
        }
    }
    __syncthreads();
    float* msm = (float*)smem;          // [4][128]
    float* vsm = msm + 512;
    float* xsm = vsm + 512;
    float* ssm = xsm + 512;
    int*   ism = (int*)(ssm + 512);

#pragma unroll
    for (int mt = 0; mt < 4; mt++) {
        float mA = -3.4e38f, mB = -3.4e38f;
#pragma unroll
        for (int nt = 0; nt < 4; nt++) {
            mA = fmaxf(mA, fmaxf(acc[mt][nt][0], acc[mt][nt][1]));
            mB = fmaxf(mB, fmaxf(acc[mt][nt][2], acc[mt][nt][3]));
        }
#pragma unroll
        for (int off = 1; off <= 2; off <<= 1) {
            mA = fmaxf(mA, __shfl_xor_sync(0xffffffffu, mA, off));
            mB = fmaxf(mB, __shfl_xor_sync(0xffffffffu, mB, off));
        }
        if ((lane & 3) == 0) {
            int r0 = wm * 64 + mt * 16 + (lane >> 2);
            msm[wn * 128 + r0] = mA;
            msm[wn * 128 + r0 + 8] = mB;
        }
    }
    __syncthreads();
#pragma unroll
    for (int mt = 0; mt < 4; mt++) {
        int r0 = wm * 64 + mt * 16 + (lane >> 2), r1 = r0 + 8;
        float MA = fmaxf(fmaxf(msm[r0], msm[128 + r0]), fmaxf(msm[256 + r0], msm[384 + r0]));
        float MB = fmaxf(fmaxf(msm[r1], msm[128 + r1]), fmaxf(msm[256 + r1], msm[384 + r1]));
        int growA = rbase + r0, growB = rbase + r1;
        float sA = 0.0f, sB = 0.0f;
        float bvA = -3.4e38f, bvB = -3.4e38f, bxA = 0.0f, bxB = 0.0f;
        int biA = 0, biB = 0;
#pragma unroll
        for (int nt = 0; nt < 4; nt++) {
            int c0 = v0 + wn * 32 + nt * 8 + (lane & 3) * 2;
            float2 nA = *(const float2*)&noise[(size_t)growA * NV + c0];
            float2 nB = *(const float2*)&noise[(size_t)growB * NV + c0];
            float x0 = acc[mt][nt][0], x1 = acc[mt][nt][1];
            float vA0 = x0 + nA.x, vA1 = x1 + nA.y;
            if (vA0 > bvA) { bvA = vA0; biA = c0; bxA = x0; }
            if (vA1 > bvA) { bvA = vA1; biA = c0 + 1; bxA = x1; }
            sA += __expf(x0 - MA) + __expf(x1 - MA);
            float x2 = acc[mt][nt][2], x3 = acc[mt][nt][3];
            float vB0 = x2 + nB.x, vB1 = x3 + nB.y;
            if (vB0 > bvB) { bvB = vB0; biB = c0; bxB = x2; }
            if (vB1 > bvB) { bvB = vB1; biB = c0 + 1; bxB = x3; }
            sB += __expf(x2 - MB) + __expf(x3 - MB);
        }
#pragma unroll
        for (int off = 1; off <= 2; off <<= 1) {
            sA += __shfl_xor_sync(0xffffffffu, sA, off);
            sB += __shfl_xor_sync(0xffffffffu, sB, off);
            float ov = __shfl_xor_sync(0xffffffffu, bvA, off);
            int oi = __shfl_xor_sync(0xffffffffu, biA, off);
            float ox = __shfl_xor_sync(0xffffffffu, bxA, off);
            if (ov > bvA || (ov == bvA && oi < biA)) { bvA = ov; biA = oi; bxA = ox; }
            ov = __shfl_xor_sync(0xffffffffu, bvB, off);
            oi = __shfl_xor_sync(0xffffffffu, biB, off);
            ox = __shfl_xor_sync(0xffffffffu, bxB, off);
            if (ov > bvB || (ov == bvB && oi < biB)) { bvB = ov; biB = oi; bxB = ox; }
        }
        if ((lane & 3) == 0) {
            vsm[wn * 128 + r0] = bvA; ism[wn * 128 + r0] = biA;
            xsm[wn * 128 + r0] = bxA; ssm[wn * 128 + r0] = sA;
            vsm[wn * 128 + r1] = bvB; ism[wn * 128 + r1] = biB;
            xsm[wn * 128 + r1] = bxB; ssm[wn * 128 + r1] = sB;
        }
    }
    __syncthreads();
    if (tid < 128) {
        int r = tid, grow = rbase + r;
        float M = fmaxf(fmaxf(msm[r], msm[128 + r]), fmaxf(msm[256 + r], msm[384 + r]));
        float S = ssm[r] + ssm[128 + r] + ssm[256 + r] + ssm[384 + r];
        float bv = vsm[r]; int bi = ism[r]; float bx = xsm[r];
#pragma unroll
        for (int w = 1; w < 4; w++) {
            float ov = vsm[w * 128 + r]; int oi = ism[w * 128 + r];
            if (ov > bv || (ov == bv && oi < bi)) { bv = ov; bi = oi; bx = xsm[w * 128 + r]; }
        }
        g_partA[grow * 4 + blockIdx.x] = make_float4(bv, __int_as_float(bi), bx, M);
        g_partB[grow * 4 + blockIdx.x] = S;
    }
}

// ---------------- fin: combine step 15 + outputs ----------------
__global__ void fin_kernel(float* __restrict__ out) {
    int b = blockIdx.x * blockDim.x + threadIdx.x;
    if (b < NB) {
        float lp;
        int tok = combine_row(b, &lp);
        int alive = g_alive[1][b];
        int tok_out = alive ? tok : 0;
        float logp = g_logp[b] + (alive ? lp : 0.0f);
        out[(size_t)b * NT + 15] = (float)tok_out;
        out[NB * NT + b] = (float)g_N[b];
        out[NB * NT + NB + b] = logp;
    }
}

extern "C" void kernel_launch(void* const* d_in, const int* in_sizes, int n_in,
                              void* d_out, int out_size) {
    const int* actions = (const int*)d_in[0];
    const float* h1 = (const float*)d_in[2];
    const float* d2e = (const float*)d_in[3];
    const float* Wih = (const float*)d_in[4];
    const float* Whh = (const float*)d_in[5];
    const float* bih = (const float*)d_in[6];
    const float* bhh = (const float*)d_in[7];
    const float* Wout = (const float*)d_in[8];
    const float* bout = (const float*)d_in[9];
    float* out = (float*)d_out;

    static cudaStream_t s_side = nullptr;
    static cudaEvent_t s_evRoot = nullptr;
    static cudaEvent_t s_evN[NT];
    if (!s_side) {
        int loPrio = 0, hiPrio = 0;
        cudaDeviceGetStreamPriorityRange(&loPrio, &hiPrio);
        cudaStreamCreateWithPriority(&s_side, cudaStreamNonBlocking, loPrio);
        cudaEventCreateWithFlags(&s_evRoot, cudaEventDisableTiming);
        for (int t = 0; t < NT; t++)
            cudaEventCreateWithFlags(&s_evN[t], cudaEventDisableTiming);
        cudaFuncSetAttribute(k1_mma, cudaFuncAttributeMaxDynamicSharedMemorySize, K1_SMEM);
        cudaFuncSetAttribute(k2_mma, cudaFuncAttributeMaxDynamicSharedMemorySize, K2_SMEM);
    }

    prep_kernel<<<1024, 256>>>(Wih, Whh, Wout);
    tgemm_kernel<<<64, 256>>>(d2e, bih, bhh);
    init_kernel<<<2048, 256>>>(actions, h1);

    cudaEventRecord(s_evRoot, 0);
    cudaStreamWaitEvent(s_side, s_evRoot, 0);
    for (int t = 0; t < NT; t++) {
        noise_kernel<<<NB * NV / 4 / 256, 256, 0, s_side>>>(t);
        cudaEventRecord(s_evN[t], s_side);
    }

    for (int t = 0; t < NT; t++) {
        k1_mma<<<dim3(8, 256), 256, K1_SMEM>>>(t, bhh, out);
        cudaStreamWaitEvent(0, s_evN[t], 0);
        k2_mma<<<dim3(4, 128), 256, K2_SMEM>>>(t, bout);
    }
    fin_kernel<<<64, 256>>>(out);
}